// round 11
// baseline (speedup 1.0000x reference)
#include <cuda_runtime.h>
#include <cuda_bf16.h>
#include <math.h>
#include <float.h>
#include <stdint.h>

// Problem constants
#define BB 2
#define LL 2048
#define DD 1024
#define HH 16
#define HD 64
#define TOPU 40
#define MM (BB*LL)
#define SCALE 0.125f

// ---------------- scratch ----------------
__device__ float g_qkv[3][MM*DD];
__device__ __nv_bfloat16 g_xh[3][MM*DD];
__device__ __nv_bfloat16 g_xl[3][MM*DD];
__device__ __nv_bfloat16 g_wh[3][DD*DD];
__device__ __nv_bfloat16 g_wl[3][DD*DD];
__device__ __nv_bfloat16 g_qkh[2][MM*DD];   // bf16 planes of projected Q,K
__device__ __nv_bfloat16 g_qkl[2][MM*DD];
__device__ float g_sp[BB*HH*LL];
__device__ int g_topk[BB*HH*TOPU];
__device__ unsigned g_selmask[BB*LL];
__device__ int g_selu[BB*LL*HH];
__device__ float g_ctx[BB*HH*TOPU*HD];
__device__ float g_base[BB*DD];
__device__ float g_baseout[BB*DD];

// ---------------- helpers ----------------
__device__ __forceinline__ uint32_t smem_u32(const void* p) {
    uint32_t a;
    asm("{ .reg .u64 t; cvta.to.shared.u64 t, %1; cvt.u32.u64 %0, t; }" : "=r"(a) : "l"(p));
    return a;
}
__device__ __forceinline__ void ldsm4(uint32_t r[4], uint32_t addr) {
    asm volatile("ldmatrix.sync.aligned.m8n8.x4.shared.b16 {%0,%1,%2,%3}, [%4];"
        : "=r"(r[0]), "=r"(r[1]), "=r"(r[2]), "=r"(r[3]) : "r"(addr));
}
__device__ __forceinline__ void mma16816(float c[4], const uint32_t a[4], const uint32_t b[2]) {
    asm volatile("mma.sync.aligned.m16n8k16.row.col.f32.bf16.bf16.f32 "
        "{%0,%1,%2,%3},{%4,%5,%6,%7},{%8,%9},{%0,%1,%2,%3};"
        : "+f"(c[0]), "+f"(c[1]), "+f"(c[2]), "+f"(c[3])
        : "r"(a[0]), "r"(a[1]), "r"(a[2]), "r"(a[3]), "r"(b[0]), "r"(b[1]));
}
__device__ __forceinline__ void cpa16(uint32_t dst, const void* src) {
    asm volatile("cp.async.cg.shared.global [%0], [%1], 16;" :: "r"(dst), "l"(src) : "memory");
}
__device__ __forceinline__ void cpa_commit() {
    asm volatile("cp.async.commit_group;" ::: "memory");
}
template <int N> __device__ __forceinline__ void cpa_wait() {
    asm volatile("cp.async.wait_group %0;" :: "n"(N) : "memory");
}

// fp32x4 -> packed bf16 hi plane + lo plane (2-way split)
__device__ __forceinline__ void split_pack(float4 v, uint2& hi, uint2& lo) {
    __nv_bfloat16 bx = __float2bfloat16_rn(v.x);
    __nv_bfloat16 by = __float2bfloat16_rn(v.y);
    __nv_bfloat16 bz = __float2bfloat16_rn(v.z);
    __nv_bfloat16 bw = __float2bfloat16_rn(v.w);
    hi.x = ((uint32_t)__bfloat16_as_ushort(by) << 16) | __bfloat16_as_ushort(bx);
    hi.y = ((uint32_t)__bfloat16_as_ushort(bw) << 16) | __bfloat16_as_ushort(bz);
    __nv_bfloat16 lx = __float2bfloat16_rn(v.x - __bfloat162float(bx));
    __nv_bfloat16 ly = __float2bfloat16_rn(v.y - __bfloat162float(by));
    __nv_bfloat16 lz = __float2bfloat16_rn(v.z - __bfloat162float(bz));
    __nv_bfloat16 lw = __float2bfloat16_rn(v.w - __bfloat162float(bw));
    lo.x = ((uint32_t)__bfloat16_as_ushort(ly) << 16) | __bfloat16_as_ushort(lx);
    lo.y = ((uint32_t)__bfloat16_as_ushort(lw) << 16) | __bfloat16_as_ushort(lz);
}

// ================= split inputs: fp32 -> (hi, lo) bf16 planes =================
__global__ __launch_bounds__(256) void split_kernel(
    const float* __restrict__ s0, const float* __restrict__ s1, const float* __restrict__ s2,
    int base) {
    const int sid = base + blockIdx.y;
    const float* s = (blockIdx.y == 0) ? s0 : (blockIdx.y == 1) ? s1 : s2;
    __nv_bfloat16 *dh, *dl;
    int n4;
    if (sid < 3) { dh = g_xh[sid]; dl = g_xl[sid]; n4 = MM * DD / 4; }
    else         { dh = g_wh[sid - 3]; dl = g_wl[sid - 3]; n4 = DD * DD / 4; }
    int idx = blockIdx.x * 256 + threadIdx.x;
    if (idx >= n4) return;
    float4 val = ((const float4*)s)[idx];
    uint2 hi, lo;
    split_pack(val, hi, lo);
    ((uint2*)dh)[idx] = hi;
    ((uint2*)dl)[idx] = lo;
}

// ================= fused projections via cp.async + mma.sync ==================
// grid (8 ntiles, 32 mtiles, 3), 256 threads (8 warps, warp tile 32x64).
// SW64-swizzled 64B rows -> stage 32KB; 3 stages; (256,2) -> 2 blocks/SM.
#define PROJ_STG 32768
#define PROJ_DSMEM (3*PROJ_STG)

__global__ void __launch_bounds__(256, 2) proj_mma(
    const float* __restrict__ bi0, const float* __restrict__ bi1, const float* __restrict__ bi2) {
    extern __shared__ char sm[];
    const uint32_t sb = smem_u32(sm);
    const int z = blockIdx.z;
    const float* bias = (z == 0) ? bi0 : (z == 1) ? bi1 : bi2;
    float* __restrict__ Y = g_qkv[z];
    const int tid = threadIdx.x, lane = tid & 31, wid = tid >> 5;
    const int bm = blockIdx.y * 128, bn = blockIdx.x * 128;
    const int m0 = (wid >> 1) * 32, n0 = (wid & 1) * 64;

    float c[2][8][4];
#pragma unroll
    for (int i = 0; i < 2; ++i)
#pragma unroll
        for (int j = 0; j < 8; ++j)
#pragma unroll
            for (int k = 0; k < 4; ++k) c[i][j][k] = 0.f;

    // cp.async addressing: 2 (row,seg) slots/thread, 4 planes each; swizzle is
    // static per thread: dst = plane*8192 + r*64 + ((seg ^ ((r>>1)&3))<<4)
    const char* pXh[2]; const char* pXl[2]; const char* pWh[2]; const char* pWl[2];
    uint32_t doff[2];
#pragma unroll
    for (int i = 0; i < 2; ++i) {
        int idx = tid + 256 * i;
        int r = idx >> 2, seg = idx & 3;
        pXh[i] = (const char*)(g_xh[z] + (size_t)(bm + r) * DD + seg * 8);
        pXl[i] = (const char*)(g_xl[z] + (size_t)(bm + r) * DD + seg * 8);
        pWh[i] = (const char*)(g_wh[z] + (size_t)(bn + r) * DD + seg * 8);
        pWl[i] = (const char*)(g_wl[z] + (size_t)(bn + r) * DD + seg * 8);
        doff[i] = (uint32_t)r * 64 + (uint32_t)((seg ^ ((r >> 1) & 3)) << 4);
    }

    auto issue = [&](int kt) {
        uint32_t off = (uint32_t)kt * 64;
        uint32_t stg = sb + (uint32_t)(kt % 3) * PROJ_STG;
#pragma unroll
        for (int i = 0; i < 2; ++i) {
            uint32_t base = stg + doff[i];
            cpa16(base, pXh[i] + off);
            cpa16(base + 8192, pXl[i] + off);
            cpa16(base + 16384, pWh[i] + off);
            cpa16(base + 24576, pWl[i] + off);
        }
        cpa_commit();
    };

    // ldsm addressing (SW64): addr = plane + r*64 + ((slot ^ ((r>>1)&3))<<4)
    const int hi16 = (lane >> 4) & 1;
    uint32_t aRB[2]; int aX[2];
#pragma unroll
    for (int i = 0; i < 2; ++i) {
        int r = m0 + (lane & 15) + i * 16;
        aRB[i] = (uint32_t)r * 64;
        aX[i] = (r >> 1) & 3;
    }
    uint32_t bRB[4]; int bX[4];
#pragma unroll
    for (int jh = 0; jh < 4; ++jh) {
        int r = n0 + jh * 16 + (lane & 15);
        bRB[jh] = (uint32_t)r * 64;
        bX[jh] = (r >> 1) & 3;
    }

    issue(0); issue(1);

#pragma unroll 1
    for (int kt = 0; kt < 32; ++kt) {
        if (kt < 31) cpa_wait<1>();
        else cpa_wait<0>();
        __syncthreads();
        if (kt + 2 < 32) issue(kt + 2);

        const uint32_t A = sb + (uint32_t)(kt % 3) * PROJ_STG;
#pragma unroll
        for (int s = 0; s < 2; ++s) {
            const int slot = s * 2 + hi16;
            uint32_t ah[2][4], al[2][4];
#pragma unroll
            for (int i = 0; i < 2; ++i) {
                uint32_t ao = aRB[i] + (uint32_t)((slot ^ aX[i]) << 4);
                ldsm4(ah[i], A + ao);
                ldsm4(al[i], A + 8192 + ao);
            }
#pragma unroll
            for (int jh = 0; jh < 4; ++jh) {
                uint32_t bo = bRB[jh] + (uint32_t)((slot ^ bX[jh]) << 4);
                uint32_t bh[2][2], bl[2][2];
                {
                    uint32_t q[4];
                    ldsm4(q, A + 16384 + bo);
                    bh[0][0] = q[0]; bh[0][1] = q[2]; bh[1][0] = q[1]; bh[1][1] = q[3];
                    ldsm4(q, A + 24576 + bo);
                    bl[0][0] = q[0]; bl[0][1] = q[2]; bl[1][0] = q[1]; bl[1][1] = q[3];
                }
#pragma unroll
                for (int i = 0; i < 2; ++i)
#pragma unroll
                    for (int jj = 0; jj < 2; ++jj) {
                        float* cc = c[i][jh * 2 + jj];
                        mma16816(cc, ah[i], bh[jj]);
                        mma16816(cc, ah[i], bl[jj]);
                        mma16816(cc, al[i], bh[jj]);
                    }
            }
        }
    }

    // epilogue: fragments -> fp32 Y (+bias); for Q,K also bf16 hi/lo planes
    __nv_bfloat16* qh = (z < 2) ? g_qkh[z] : 0;
    __nv_bfloat16* ql = (z < 2) ? g_qkl[z] : 0;
#pragma unroll
    for (int i = 0; i < 2; ++i) {
        int r0 = bm + m0 + i * 16 + (lane >> 2);
#pragma unroll
        for (int j = 0; j < 8; ++j) {
            int col = bn + n0 + j * 8 + (lane & 3) * 2;
            float bx = bias[col], by = bias[col + 1];
#pragma unroll
            for (int hh = 0; hh < 2; ++hh) {
                int rr = r0 + hh * 8;
                float v0 = c[i][j][hh * 2] + bx, v1 = c[i][j][hh * 2 + 1] + by;
                *(float2*)(Y + (size_t)rr * DD + col) = make_float2(v0, v1);
                if (z < 2) {
                    __nv_bfloat16 h0 = __float2bfloat16_rn(v0);
                    __nv_bfloat16 h1 = __float2bfloat16_rn(v1);
                    __nv_bfloat16 l0 = __float2bfloat16_rn(v0 - __bfloat162float(h0));
                    __nv_bfloat16 l1 = __float2bfloat16_rn(v1 - __bfloat162float(h1));
                    *(uint32_t*)(qh + (size_t)rr * DD + col) =
                        ((uint32_t)__bfloat16_as_ushort(h1) << 16) | __bfloat16_as_ushort(h0);
                    *(uint32_t*)(ql + (size_t)rr * DD + col) =
                        ((uint32_t)__bfloat16_as_ushort(l1) << 16) | __bfloat16_as_ushort(l0);
                }
            }
        }
    }
}

// ================= sparsity via cp.async + mma.sync (3-stage) =================
// grid (16 qtiles, 16 h, 2 b), 512 thr (16 warps: 8 m x 2 n, warp tile 16x32).
// Q (128x64) planes resident (36KB); K chunks of 64 keys, 3 stages x 18KB.
#define SPQ 18432
#define SPK0 36864
#define SPK_STG 18432
#define SP_DSMEM (SPK0 + 3*SPK_STG)

__global__ void __launch_bounds__(512, 2) sparsity_mma() {
    extern __shared__ char sm[];
    const uint32_t sb = smem_u32(sm);
    __shared__ float sred[2][128][2];
    const int tid = threadIdx.x, lane = tid & 31, wid = tid >> 5;
    const int b = blockIdx.z, h = blockIdx.y, q0 = blockIdx.x * 128;
    const int m0 = (wid >> 1) * 16, nh = wid & 1, n0 = nh * 32;
    const __nv_bfloat16* __restrict__ Qh = g_qkh[0];
    const __nv_bfloat16* __restrict__ Ql = g_qkl[0];
    const __nv_bfloat16* __restrict__ Kh = g_qkh[1];
    const __nv_bfloat16* __restrict__ Kl = g_qkl[1];

    auto issueK = [&](int kt) {
        uint32_t base = sb + SPK0 + (uint32_t)(kt % 3) * SPK_STG;
        int r = tid >> 3, seg = tid & 7;
        uint32_t doff = (uint32_t)r * 144 + seg * 16;
        size_t src = (size_t)(b * LL + kt * 64 + r) * DD + h * HD + seg * 8;
        cpa16(base + doff, Kh + src);
        cpa16(base + 9216 + doff, Kl + src);
        cpa_commit();
    };

    // prologue: Q planes + K chunk 0 in one group, then K chunk 1
    {
#pragma unroll
        for (int i = 0; i < 2; ++i) {
            int idx = tid + 512 * i;
            int r = idx >> 3, seg = idx & 7;
            uint32_t doff = (uint32_t)r * 144 + seg * 16;
            size_t src = (size_t)(b * LL + q0 + r) * DD + h * HD + seg * 8;
            cpa16(sb + doff, Qh + src);
            cpa16(sb + SPQ + doff, Ql + src);
        }
    }
    issueK(0);
    issueK(1);

    const uint32_t arow = sb + (uint32_t)(m0 + (lane & 15)) * 144 + ((lane & 16) ? 16 : 0);
    const uint32_t brow[2] = {
        (uint32_t)(n0 + (lane & 15)) * 144 + ((lane & 16) ? 16 : 0),
        (uint32_t)(n0 + 16 + (lane & 15)) * 144 + ((lane & 16) ? 16 : 0) };

    float rmax[2] = {-FLT_MAX, -FLT_MAX}, rsum[2] = {0.f, 0.f};

#pragma unroll 1
    for (int kt = 0; kt < 32; ++kt) {
        if (kt < 31) cpa_wait<1>();
        else cpa_wait<0>();
        __syncthreads();
        if (kt + 2 < 32) issueK(kt + 2);

        const uint32_t K = sb + SPK0 + (uint32_t)(kt % 3) * SPK_STG;
        float c[4][4];
#pragma unroll
        for (int j = 0; j < 4; ++j)
#pragma unroll
            for (int k = 0; k < 4; ++k) c[j][k] = 0.f;

#pragma unroll
        for (int s = 0; s < 4; ++s) {
            const uint32_t ko = s * 32;
            uint32_t ah[4], al[4];
            ldsm4(ah, arow + ko);
            ldsm4(al, arow + SPQ + ko);
#pragma unroll
            for (int jh = 0; jh < 2; ++jh) {
                uint32_t bh[2][2], bl[2][2];
                {
                    uint32_t q[4];
                    ldsm4(q, K + brow[jh] + ko);
                    bh[0][0] = q[0]; bh[0][1] = q[2]; bh[1][0] = q[1]; bh[1][1] = q[3];
                    ldsm4(q, K + 9216 + brow[jh] + ko);
                    bl[0][0] = q[0]; bl[0][1] = q[2]; bl[1][0] = q[1]; bl[1][1] = q[3];
                }
#pragma unroll
                for (int jj = 0; jj < 2; ++jj) {
                    float* cc = c[jh * 2 + jj];
                    mma16816(cc, ah, bh[jj]);
                    mma16816(cc, ah, bl[jj]);
                    mma16816(cc, al, bh[jj]);
                }
            }
        }
#pragma unroll
        for (int j = 0; j < 4; ++j) {
#pragma unroll
            for (int hh = 0; hh < 2; ++hh) {
                float x = c[j][hh * 2], y = c[j][hh * 2 + 1];
                rmax[hh] = fmaxf(rmax[hh], fmaxf(x, y));
                rsum[hh] += x + y;
            }
        }
    }

    // reduce across quad lanes (different key columns, same row)
#pragma unroll
    for (int s = 0; s < 2; ++s) {
        rmax[s] = fmaxf(rmax[s], __shfl_xor_sync(0xffffffffu, rmax[s], 1));
        rmax[s] = fmaxf(rmax[s], __shfl_xor_sync(0xffffffffu, rmax[s], 2));
        rsum[s] += __shfl_xor_sync(0xffffffffu, rsum[s], 1);
        rsum[s] += __shfl_xor_sync(0xffffffffu, rsum[s], 2);
    }
    if ((lane & 3) == 0) {
#pragma unroll
        for (int s = 0; s < 2; ++s) {
            int row = m0 + s * 8 + (lane >> 2);
            sred[0][row][nh] = rmax[s];
            sred[1][row][nh] = rsum[s];
        }
    }
    __syncthreads();
    if (tid < 128) {
        float m = fmaxf(sred[0][tid][0], sred[0][tid][1]);
        float su = sred[1][tid][0] + sred[1][tid][1];
        g_sp[(b * HH + h) * LL + q0 + tid] = SCALE * m - SCALE * su * (1.0f / (float)LL);
    }
}

// ---------------- clear selection mask ----------------
__global__ void clear_kernel() {
    int i = blockIdx.x * 256 + threadIdx.x;
    if (i < BB * LL) g_selmask[i] = 0u;
}

// ---------------- top-40 per (b,h) ----------------
__global__ __launch_bounds__(256) void topk_kernel() {
    const int bh = blockIdx.x;
    const int b = bh >> 4, h = bh & 15;
    __shared__ float sp[LL];
    __shared__ float rv[8];
    __shared__ int ri[8];
    const int tid = threadIdx.x;
    for (int j = tid; j < LL; j += 256) sp[j] = g_sp[bh * LL + j];
    __syncthreads();
    for (int it = 0; it < TOPU; ++it) {
        float bv = -FLT_MAX; int bi = 1 << 30;
        for (int j = tid; j < LL; j += 256) {
            float v = sp[j];
            if (v > bv || (v == bv && j < bi)) { bv = v; bi = j; }
        }
#pragma unroll
        for (int o = 16; o > 0; o >>= 1) {
            float ov = __shfl_xor_sync(0xffffffffu, bv, o);
            int oi = __shfl_xor_sync(0xffffffffu, bi, o);
            if (ov > bv || (ov == bv && oi < bi)) { bv = ov; bi = oi; }
        }
        if ((tid & 31) == 0) { rv[tid >> 5] = bv; ri[tid >> 5] = bi; }
        __syncthreads();
        if (tid == 0) {
            float mv = -FLT_MAX; int mi = 1 << 30;
            for (int w = 0; w < 8; ++w)
                if (rv[w] > mv || (rv[w] == mv && ri[w] < mi)) { mv = rv[w]; mi = ri[w]; }
            g_topk[bh * TOPU + it] = mi;
            sp[mi] = -FLT_MAX;
            int row = b * LL + mi;
            atomicOr(&g_selmask[row], 1u << h);
            g_selu[row * HH + h] = it;
        }
        __syncthreads();
    }
}

// ---------------- attention over the top queries (8 q / block) ----------------
#define AQ 8
#define ATTN_DSMEM (AQ * LL * 4)

__global__ __launch_bounds__(256) void attn_kernel() {
    const int b = blockIdx.z, h = blockIdx.y, ut = blockIdx.x;
    const int bh = b * HH + h;
    extern __shared__ float P[];             // [AQ][LL] 64KB
    __shared__ float Qs[AQ][64];
    __shared__ float red[AQ][8];
    __shared__ float gmx[AQ], gsm[AQ];
    __shared__ float cred[8][AQ][64];
    const float* __restrict__ gq = g_qkv[0];
    const float* __restrict__ gk = g_qkv[1];
    const float* __restrict__ gv = g_qkv[2];
    const int tid = threadIdx.x, lane = tid & 31, wp = tid >> 5;
#pragma unroll
    for (int rep = 0; rep < 2; ++rep) {
        int idx = tid + 256 * rep;
        int u = idx >> 6, d = idx & 63;
        int qi = g_topk[bh * TOPU + ut * AQ + u];
        Qs[u][d] = gq[((size_t)(b * LL + qi)) * DD + h * HD + d];
    }
    __syncthreads();
    const float* Kb = gk + (size_t)(b * LL) * DD + h * HD;
    float lm[AQ];
#pragma unroll
    for (int u = 0; u < AQ; ++u) lm[u] = -FLT_MAX;
#pragma unroll 1
    for (int j = 0; j < 8; ++j) {
        int k = tid + 256 * j;
        const float4* kr = (const float4*)(Kb + (size_t)k * DD);
        float s[AQ];
#pragma unroll
        for (int u = 0; u < AQ; ++u) s[u] = 0.f;
#pragma unroll
        for (int dv = 0; dv < 16; ++dv) {
            float4 kv = kr[dv];
#pragma unroll
            for (int u = 0; u < AQ; ++u)
                s[u] += Qs[u][dv * 4 + 0] * kv.x + Qs[u][dv * 4 + 1] * kv.y +
                        Qs[u][dv * 4 + 2] * kv.z + Qs[u][dv * 4 + 3] * kv.w;
        }
#pragma unroll
        for (int u = 0; u < AQ; ++u) {
            float sv = s[u] * SCALE;
            P[u * LL + k] = sv;
            lm[u] = fmaxf(lm[u], sv);
        }
    }
#pragma unroll
    for (int u = 0; u < AQ; ++u) {
#pragma unroll
        for (int o = 16; o > 0; o >>= 1) lm[u] = fmaxf(lm[u], __shfl_xor_sync(0xffffffffu, lm[u], o));
        if (lane == 0) red[u][wp] = lm[u];
    }
    __syncthreads();
    if (tid < AQ) {
        float m = red[tid][0];
        for (int w = 1; w < 8; ++w) m = fmaxf(m, red[tid][w]);
        gmx[tid] = m;
    }
    __syncthreads();
    float ls[AQ];
#pragma unroll
    for (int u = 0; u < AQ; ++u) ls[u] = 0.f;
#pragma unroll 1
    for (int j = 0; j < 8; ++j) {
        int k = tid + 256 * j;
#pragma unroll
        for (int u = 0; u < AQ; ++u) {
            float e = expf(P[u * LL + k] - gmx[u]);
            P[u * LL + k] = e;
            ls[u] += e;
        }
    }
#pragma unroll
    for (int u = 0; u < AQ; ++u) {
#pragma unroll
        for (int o = 16; o > 0; o >>= 1) ls[u] += __shfl_xor_sync(0xffffffffu, ls[u], o);
        if (lane == 0) red[u][wp] = ls[u];
    }
    __syncthreads();
    if (tid < AQ) {
        float s = 0.f;
        for (int w = 0; w < 8; ++w) s += red[tid][w];
        gsm[tid] = s;
    }
    __syncthreads();
    const float* Vb = gv + (size_t)(b * LL) * DD + h * HD;
    const int d0 = lane * 2;
    float c[AQ][2];
#pragma unroll
    for (int u = 0; u < AQ; ++u) { c[u][0] = 0.f; c[u][1] = 0.f; }
    const int k0 = wp * 256;
#pragma unroll 1
    for (int kk = 0; kk < 256; ++kk) {
        int k = k0 + kk;
        float2 v = *(const float2*)(Vb + (size_t)k * DD + d0);
#pragma unroll
        for (int u = 0; u < AQ; ++u) {
            float p = P[u * LL + k];
            c[u][0] += p * v.x;
            c[u][1] += p * v.y;
        }
    }
#pragma unroll
    for (int u = 0; u < AQ; ++u) {
        cred[wp][u][d0] = c[u][0];
        cred[wp][u][d0 + 1] = c[u][1];
    }
    __syncthreads();
#pragma unroll
    for (int rep = 0; rep < 2; ++rep) {
        int idx = tid + 256 * rep;
        int u = idx >> 6, d = idx & 63;
        float s = 0.f;
#pragma unroll
        for (int w = 0; w < 8; ++w) s += cred[w][u][d];
        g_ctx[((size_t)bh * TOPU + ut * AQ + u) * HD + d] = s / gsm[u];
    }
}

// ---------------- base = mean(V) over sequence ----------------
__global__ void base_kernel() {
    int b = blockIdx.y;
    int c = blockIdx.x * 256 + threadIdx.x;
    const float* p = g_qkv[2] + (size_t)b * LL * DD + c;
    float s = 0.f;
    for (int l = 0; l < LL; ++l) s += p[(size_t)l * DD];
    g_base[b * DD + c] = s * (1.0f / (float)LL);
}

// ---------------- base_out = base_row @ Wo^T + bo ----------------
__global__ __launch_bounds__(256) void baseout_kernel(const float* __restrict__ Wo,
                                                      const float* __restrict__ bo) {
    int b = blockIdx.y;
    int n = blockIdx.x * 256 + threadIdx.x;
    __shared__ float br[DD];
    for (int j = threadIdx.x; j < DD; j += 256) br[j] = g_base[b * DD + j];
    __syncthreads();
    const float4* wr = (const float4*)(Wo + (size_t)n * DD);
    const float4* b4 = (const float4*)br;
    float s = bo[n];
    for (int c = 0; c < DD / 4; ++c) {
        float4 w = wr[c], v = b4[c];
        s += w.x * v.x + w.y * v.y + w.z * v.z + w.w * v.w;
    }
    g_baseout[b * DD + n] = s;
}

// ---------------- final output ----------------
__global__ __launch_bounds__(256) void output_kernel(const float* __restrict__ Wo,
                                                     float* __restrict__ out) {
    const int row = blockIdx.x;
    const int b = row >> 11;
    const int tid = threadIdx.x;
    __shared__ float delta[HD];
    float o[4];
    *(float4*)o = *(const float4*)(g_baseout + b * DD + tid * 4);
    unsigned mask = g_selmask[row];
    while (mask) {
        int h = __ffs(mask) - 1;
        mask &= mask - 1;
        int u = g_selu[row * HH + h];
        if (tid < HD) {
            int bh = b * HH + h;
            delta[tid] = g_ctx[((size_t)bh * TOPU + u) * HD + tid] - g_base[b * DD + h * HD + tid];
        }
        __syncthreads();
        const float* wr = Wo + (size_t)tid * 4 * DD + h * HD;
#pragma unroll
        for (int j = 0; j < 4; ++j) {
            const float4* w4 = (const float4*)(wr + (size_t)j * DD);
            float s = 0.f;
#pragma unroll
            for (int d4 = 0; d4 < HD / 4; ++d4) {
                float4 w = w4[d4];
                s += w.x * delta[d4 * 4 + 0] + w.y * delta[d4 * 4 + 1] +
                     w.z * delta[d4 * 4 + 2] + w.w * delta[d4 * 4 + 3];
            }
            o[j] += s;
        }
        __syncthreads();
    }
    *(float4*)(out + (size_t)row * DD + tid * 4) = make_float4(o[0], o[1], o[2], o[3]);
}

// ---------------- launch ----------------
extern "C" void kernel_launch(void* const* d_in, const int* in_sizes, int n_in,
                              void* d_out, int out_size) {
    const float* query = (const float*)d_in[0];
    const float* key_t = (const float*)d_in[1];
    const float* value = (const float*)d_in[2];
    const float* Wq = (const float*)d_in[3];
    const float* bq = (const float*)d_in[4];
    const float* Wk = (const float*)d_in[5];
    const float* bk = (const float*)d_in[6];
    const float* Wv = (const float*)d_in[7];
    const float* bv = (const float*)d_in[8];
    const float* Wo = (const float*)d_in[9];
    const float* bo = (const float*)d_in[10];
    float* out = (float*)d_out;

    cudaFuncSetAttribute(proj_mma, cudaFuncAttributeMaxDynamicSharedMemorySize, PROJ_DSMEM);
    cudaFuncSetAttribute(sparsity_mma, cudaFuncAttributeMaxDynamicSharedMemorySize, SP_DSMEM);
    cudaFuncSetAttribute(attn_kernel, cudaFuncAttributeMaxDynamicSharedMemorySize, ATTN_DSMEM);

    // launch order: proj_mma is the 4th launch (ncu profiles #4)
    split_kernel<<<dim3(4096, 3), 256>>>(query, key_t, value, 0);     // 1: X planes
    split_kernel<<<dim3(1024, 3), 256>>>(Wq, Wk, Wv, 3);              // 2: W planes
    clear_kernel<<<(BB * LL + 255) / 256, 256>>>();                   // 3
    proj_mma<<<dim3(8, 32, 3), 256, PROJ_DSMEM>>>(bq, bk, bv);        // 4 (profiled)
    sparsity_mma<<<dim3(LL / 128, HH, BB), 512, SP_DSMEM>>>();        // 5
    topk_kernel<<<BB * HH, 256>>>();                                  // 6
    attn_kernel<<<dim3(TOPU / AQ, HH, BB), 256, ATTN_DSMEM>>>();      // 7
    base_kernel<<<dim3(DD / 256, BB), 256>>>();                       // 8
    baseout_kernel<<<dim3(DD / 256, BB), 256>>>(Wo, bo);              // 9
    output_kernel<<<BB * LL, 256>>>(Wo, out);                         // 10
}

// round 12
// speedup vs baseline: 1.0867x; 1.0867x over previous
#include <cuda_runtime.h>
#include <cuda_bf16.h>
#include <math.h>
#include <float.h>
#include <stdint.h>

// Problem constants
#define BB 2
#define LL 2048
#define DD 1024
#define HH 16
#define HD 64
#define TOPU 40
#define MM (BB*LL)
#define SCALE 0.125f

// ---------------- scratch ----------------
__device__ float g_qkv[3][MM*DD];
__device__ __nv_bfloat16 g_xh[3][MM*DD];
__device__ __nv_bfloat16 g_xl[3][MM*DD];
__device__ __nv_bfloat16 g_wh[3][DD*DD];
__device__ __nv_bfloat16 g_wl[3][DD*DD];
__device__ __nv_bfloat16 g_qkh[2][MM*DD];   // bf16 planes of projected Q,K
__device__ __nv_bfloat16 g_qkl[2][MM*DD];
__device__ float g_sp[BB*HH*LL];
__device__ int g_topk[BB*HH*TOPU];
__device__ unsigned g_selmask[BB*LL];
__device__ int g_selu[BB*LL*HH];
__device__ float g_ctx[BB*HH*TOPU*HD];
__device__ float g_base[BB*DD];
__device__ float g_baseout[BB*DD];

// ---------------- helpers ----------------
__device__ __forceinline__ uint32_t smem_u32(const void* p) {
    uint32_t a;
    asm("{ .reg .u64 t; cvta.to.shared.u64 t, %1; cvt.u32.u64 %0, t; }" : "=r"(a) : "l"(p));
    return a;
}
__device__ __forceinline__ void ldsm4(uint32_t r[4], uint32_t addr) {
    asm volatile("ldmatrix.sync.aligned.m8n8.x4.shared.b16 {%0,%1,%2,%3}, [%4];"
        : "=r"(r[0]), "=r"(r[1]), "=r"(r[2]), "=r"(r[3]) : "r"(addr));
}
__device__ __forceinline__ void mma16816(float c[4], const uint32_t a[4], const uint32_t b[2]) {
    asm volatile("mma.sync.aligned.m16n8k16.row.col.f32.bf16.bf16.f32 "
        "{%0,%1,%2,%3},{%4,%5,%6,%7},{%8,%9},{%0,%1,%2,%3};"
        : "+f"(c[0]), "+f"(c[1]), "+f"(c[2]), "+f"(c[3])
        : "r"(a[0]), "r"(a[1]), "r"(a[2]), "r"(a[3]), "r"(b[0]), "r"(b[1]));
}
__device__ __forceinline__ void cpa16(uint32_t dst, const void* src) {
    asm volatile("cp.async.cg.shared.global [%0], [%1], 16;" :: "r"(dst), "l"(src) : "memory");
}
__device__ __forceinline__ void cpa_commit() {
    asm volatile("cp.async.commit_group;" ::: "memory");
}
template <int N> __device__ __forceinline__ void cpa_wait() {
    asm volatile("cp.async.wait_group %0;" :: "n"(N) : "memory");
}

// fp32x4 -> packed bf16 hi plane + lo plane (2-way split)
__device__ __forceinline__ void split_pack(float4 v, uint2& hi, uint2& lo) {
    __nv_bfloat16 bx = __float2bfloat16_rn(v.x);
    __nv_bfloat16 by = __float2bfloat16_rn(v.y);
    __nv_bfloat16 bz = __float2bfloat16_rn(v.z);
    __nv_bfloat16 bw = __float2bfloat16_rn(v.w);
    hi.x = ((uint32_t)__bfloat16_as_ushort(by) << 16) | __bfloat16_as_ushort(bx);
    hi.y = ((uint32_t)__bfloat16_as_ushort(bw) << 16) | __bfloat16_as_ushort(bz);
    __nv_bfloat16 lx = __float2bfloat16_rn(v.x - __bfloat162float(bx));
    __nv_bfloat16 ly = __float2bfloat16_rn(v.y - __bfloat162float(by));
    __nv_bfloat16 lz = __float2bfloat16_rn(v.z - __bfloat162float(bz));
    __nv_bfloat16 lw = __float2bfloat16_rn(v.w - __bfloat162float(bw));
    lo.x = ((uint32_t)__bfloat16_as_ushort(ly) << 16) | __bfloat16_as_ushort(lx);
    lo.y = ((uint32_t)__bfloat16_as_ushort(lw) << 16) | __bfloat16_as_ushort(lz);
}

// ================= split inputs: fp32 -> (hi, lo) bf16 planes =================
__global__ __launch_bounds__(256) void split_kernel(
    const float* __restrict__ s0, const float* __restrict__ s1, const float* __restrict__ s2,
    int base) {
    const int sid = base + blockIdx.y;
    const float* s = (blockIdx.y == 0) ? s0 : (blockIdx.y == 1) ? s1 : s2;
    __nv_bfloat16 *dh, *dl;
    int n4;
    if (sid < 3) { dh = g_xh[sid]; dl = g_xl[sid]; n4 = MM * DD / 4; }
    else         { dh = g_wh[sid - 3]; dl = g_wl[sid - 3]; n4 = DD * DD / 4; }
    int idx = blockIdx.x * 256 + threadIdx.x;
    if (idx >= n4) return;
    float4 val = ((const float4*)s)[idx];
    uint2 hi, lo;
    split_pack(val, hi, lo);
    ((uint2*)dh)[idx] = hi;
    ((uint2*)dl)[idx] = lo;
}

// ================= fused projections via cp.async + mma.sync ==================
// grid (8 ntiles, 32 mtiles, 3), 256 threads (8 warps, warp tile 32x64).
// SW64-swizzled 64B rows -> stage 32KB; 3 stages; (256,2) -> 2 blocks/SM.
#define PROJ_STG 32768
#define PROJ_DSMEM (3*PROJ_STG)

__global__ void __launch_bounds__(256, 2) proj_mma(
    const float* __restrict__ bi0, const float* __restrict__ bi1, const float* __restrict__ bi2) {
    extern __shared__ char sm[];
    const uint32_t sb = smem_u32(sm);
    const int z = blockIdx.z;
    const float* bias = (z == 0) ? bi0 : (z == 1) ? bi1 : bi2;
    float* __restrict__ Y = g_qkv[z];
    const int tid = threadIdx.x, lane = tid & 31, wid = tid >> 5;
    const int bm = blockIdx.y * 128, bn = blockIdx.x * 128;
    const int m0 = (wid >> 1) * 32, n0 = (wid & 1) * 64;

    float c[2][8][4];
#pragma unroll
    for (int i = 0; i < 2; ++i)
#pragma unroll
        for (int j = 0; j < 8; ++j)
#pragma unroll
            for (int k = 0; k < 4; ++k) c[i][j][k] = 0.f;

    // cp.async addressing: 2 (row,seg) slots/thread, 4 planes each; swizzle is
    // static per thread: dst = plane*8192 + r*64 + ((seg ^ ((r>>1)&3))<<4)
    const char* pXh[2]; const char* pXl[2]; const char* pWh[2]; const char* pWl[2];
    uint32_t doff[2];
#pragma unroll
    for (int i = 0; i < 2; ++i) {
        int idx = tid + 256 * i;
        int r = idx >> 2, seg = idx & 3;
        pXh[i] = (const char*)(g_xh[z] + (size_t)(bm + r) * DD + seg * 8);
        pXl[i] = (const char*)(g_xl[z] + (size_t)(bm + r) * DD + seg * 8);
        pWh[i] = (const char*)(g_wh[z] + (size_t)(bn + r) * DD + seg * 8);
        pWl[i] = (const char*)(g_wl[z] + (size_t)(bn + r) * DD + seg * 8);
        doff[i] = (uint32_t)r * 64 + (uint32_t)((seg ^ ((r >> 1) & 3)) << 4);
    }

    auto issue = [&](int kt) {
        uint32_t off = (uint32_t)kt * 64;
        uint32_t stg = sb + (uint32_t)(kt % 3) * PROJ_STG;
#pragma unroll
        for (int i = 0; i < 2; ++i) {
            uint32_t base = stg + doff[i];
            cpa16(base, pXh[i] + off);
            cpa16(base + 8192, pXl[i] + off);
            cpa16(base + 16384, pWh[i] + off);
            cpa16(base + 24576, pWl[i] + off);
        }
        cpa_commit();
    };

    // ldsm addressing (SW64): addr = plane + r*64 + ((slot ^ ((r>>1)&3))<<4)
    const int hi16 = (lane >> 4) & 1;
    uint32_t aRB[2]; int aX[2];
#pragma unroll
    for (int i = 0; i < 2; ++i) {
        int r = m0 + (lane & 15) + i * 16;
        aRB[i] = (uint32_t)r * 64;
        aX[i] = (r >> 1) & 3;
    }
    uint32_t bRB[4]; int bX[4];
#pragma unroll
    for (int jh = 0; jh < 4; ++jh) {
        int r = n0 + jh * 16 + (lane & 15);
        bRB[jh] = (uint32_t)r * 64;
        bX[jh] = (r >> 1) & 3;
    }

    issue(0); issue(1);

#pragma unroll 1
    for (int kt = 0; kt < 32; ++kt) {
        if (kt < 31) cpa_wait<1>();
        else cpa_wait<0>();
        __syncthreads();
        if (kt + 2 < 32) issue(kt + 2);

        const uint32_t A = sb + (uint32_t)(kt % 3) * PROJ_STG;
#pragma unroll
        for (int s = 0; s < 2; ++s) {
            const int slot = s * 2 + hi16;
            uint32_t ah[2][4], al[2][4];
#pragma unroll
            for (int i = 0; i < 2; ++i) {
                uint32_t ao = aRB[i] + (uint32_t)((slot ^ aX[i]) << 4);
                ldsm4(ah[i], A + ao);
                ldsm4(al[i], A + 8192 + ao);
            }
#pragma unroll
            for (int jh = 0; jh < 4; ++jh) {
                uint32_t bo = bRB[jh] + (uint32_t)((slot ^ bX[jh]) << 4);
                uint32_t bh[2][2], bl[2][2];
                {
                    uint32_t q[4];
                    ldsm4(q, A + 16384 + bo);
                    bh[0][0] = q[0]; bh[0][1] = q[2]; bh[1][0] = q[1]; bh[1][1] = q[3];
                    ldsm4(q, A + 24576 + bo);
                    bl[0][0] = q[0]; bl[0][1] = q[2]; bl[1][0] = q[1]; bl[1][1] = q[3];
                }
#pragma unroll
                for (int i = 0; i < 2; ++i)
#pragma unroll
                    for (int jj = 0; jj < 2; ++jj) {
                        float* cc = c[i][jh * 2 + jj];
                        mma16816(cc, ah[i], bh[jj]);
                        mma16816(cc, ah[i], bl[jj]);
                        mma16816(cc, al[i], bh[jj]);
                    }
            }
        }
    }

    // epilogue: fragments -> fp32 Y (+bias); for Q,K also bf16 hi/lo planes
    __nv_bfloat16* qh = (z < 2) ? g_qkh[z] : 0;
    __nv_bfloat16* ql = (z < 2) ? g_qkl[z] : 0;
#pragma unroll
    for (int i = 0; i < 2; ++i) {
        int r0 = bm + m0 + i * 16 + (lane >> 2);
#pragma unroll
        for (int j = 0; j < 8; ++j) {
            int col = bn + n0 + j * 8 + (lane & 3) * 2;
            float bx = bias[col], by = bias[col + 1];
#pragma unroll
            for (int hh = 0; hh < 2; ++hh) {
                int rr = r0 + hh * 8;
                float v0 = c[i][j][hh * 2] + bx, v1 = c[i][j][hh * 2 + 1] + by;
                *(float2*)(Y + (size_t)rr * DD + col) = make_float2(v0, v1);
                if (z < 2) {
                    __nv_bfloat16 h0 = __float2bfloat16_rn(v0);
                    __nv_bfloat16 h1 = __float2bfloat16_rn(v1);
                    __nv_bfloat16 l0 = __float2bfloat16_rn(v0 - __bfloat162float(h0));
                    __nv_bfloat16 l1 = __float2bfloat16_rn(v1 - __bfloat162float(h1));
                    *(uint32_t*)(qh + (size_t)rr * DD + col) =
                        ((uint32_t)__bfloat16_as_ushort(h1) << 16) | __bfloat16_as_ushort(h0);
                    *(uint32_t*)(ql + (size_t)rr * DD + col) =
                        ((uint32_t)__bfloat16_as_ushort(l1) << 16) | __bfloat16_as_ushort(l0);
                }
            }
        }
    }
}

// ================= sparsity via cp.async + mma.sync (round-7 version) =========
// grid (16 qtiles, 16 h, 2 b), 512 thr (16 warps: 8 m x 2 n, warp tile 16x32).
// Q (128x64) planes resident (36KB); K chunks of 64 keys, 2 stages x 18KB.
#define SPQ 18432
#define SPK0 36864
#define SPK_STG 18432
#define SP_DSMEM (SPK0 + 2*SPK_STG)

__global__ void __launch_bounds__(512, 2) sparsity_mma() {
    extern __shared__ char sm[];
    const uint32_t sb = smem_u32(sm);
    __shared__ float sred[2][128][2];
    const int tid = threadIdx.x, lane = tid & 31, wid = tid >> 5;
    const int b = blockIdx.z, h = blockIdx.y, q0 = blockIdx.x * 128;
    const int m0 = (wid >> 1) * 16, nh = wid & 1, n0 = nh * 32;
    const __nv_bfloat16* __restrict__ Qh = g_qkh[0];
    const __nv_bfloat16* __restrict__ Ql = g_qkl[0];
    const __nv_bfloat16* __restrict__ Kh = g_qkh[1];
    const __nv_bfloat16* __restrict__ Kl = g_qkl[1];

    auto issueK = [&](int kt) {
        uint32_t base = sb + SPK0 + (uint32_t)(kt & 1) * SPK_STG;
        int r = tid >> 3, seg = tid & 7;
        uint32_t doff = (uint32_t)r * 144 + seg * 16;
        size_t src = (size_t)(b * LL + kt * 64 + r) * DD + h * HD + seg * 8;
        cpa16(base + doff, Kh + src);
        cpa16(base + 9216 + doff, Kl + src);
        cpa_commit();
    };

    // prologue: Q planes + K chunk 0 in one group
    {
#pragma unroll
        for (int i = 0; i < 2; ++i) {
            int idx = tid + 512 * i;
            int r = idx >> 3, seg = idx & 7;
            uint32_t doff = (uint32_t)r * 144 + seg * 16;
            size_t src = (size_t)(b * LL + q0 + r) * DD + h * HD + seg * 8;
            cpa16(sb + doff, Qh + src);
            cpa16(sb + SPQ + doff, Ql + src);
        }
    }
    issueK(0);
    cpa_wait<0>();
    __syncthreads();

    const uint32_t arow = sb + (uint32_t)(m0 + (lane & 15)) * 144 + ((lane & 16) ? 16 : 0);
    const uint32_t brow[2] = {
        (uint32_t)(n0 + (lane & 15)) * 144 + ((lane & 16) ? 16 : 0),
        (uint32_t)(n0 + 16 + (lane & 15)) * 144 + ((lane & 16) ? 16 : 0) };

    float rmax[2] = {-FLT_MAX, -FLT_MAX}, rsum[2] = {0.f, 0.f};

#pragma unroll 1
    for (int kt = 0; kt < 32; ++kt) {
        if (kt + 1 < 32) issueK(kt + 1);
        const uint32_t K = sb + SPK0 + (uint32_t)(kt & 1) * SPK_STG;
        float c[4][4];
#pragma unroll
        for (int j = 0; j < 4; ++j)
#pragma unroll
            for (int k = 0; k < 4; ++k) c[j][k] = 0.f;

#pragma unroll
        for (int s = 0; s < 4; ++s) {
            const uint32_t ko = s * 32;
            uint32_t ah[4], al[4];
            ldsm4(ah, arow + ko);
            ldsm4(al, arow + SPQ + ko);
#pragma unroll
            for (int jh = 0; jh < 2; ++jh) {
                uint32_t bh[2][2], bl[2][2];
                {
                    uint32_t q[4];
                    ldsm4(q, K + brow[jh] + ko);
                    bh[0][0] = q[0]; bh[0][1] = q[2]; bh[1][0] = q[1]; bh[1][1] = q[3];
                    ldsm4(q, K + 9216 + brow[jh] + ko);
                    bl[0][0] = q[0]; bl[0][1] = q[2]; bl[1][0] = q[1]; bl[1][1] = q[3];
                }
#pragma unroll
                for (int jj = 0; jj < 2; ++jj) {
                    float* cc = c[jh * 2 + jj];
                    mma16816(cc, ah, bh[jj]);
                    mma16816(cc, ah, bl[jj]);
                    mma16816(cc, al, bh[jj]);
                }
            }
        }
#pragma unroll
        for (int j = 0; j < 4; ++j) {
#pragma unroll
            for (int hh = 0; hh < 2; ++hh) {
                float x = c[j][hh * 2], y = c[j][hh * 2 + 1];
                rmax[hh] = fmaxf(rmax[hh], fmaxf(x, y));
                rsum[hh] += x + y;
            }
        }
        cpa_wait<0>();
        __syncthreads();
    }

    // reduce across quad lanes (different key columns, same row)
#pragma unroll
    for (int s = 0; s < 2; ++s) {
        rmax[s] = fmaxf(rmax[s], __shfl_xor_sync(0xffffffffu, rmax[s], 1));
        rmax[s] = fmaxf(rmax[s], __shfl_xor_sync(0xffffffffu, rmax[s], 2));
        rsum[s] += __shfl_xor_sync(0xffffffffu, rsum[s], 1);
        rsum[s] += __shfl_xor_sync(0xffffffffu, rsum[s], 2);
    }
    if ((lane & 3) == 0) {
#pragma unroll
        for (int s = 0; s < 2; ++s) {
            int row = m0 + s * 8 + (lane >> 2);
            sred[0][row][nh] = rmax[s];
            sred[1][row][nh] = rsum[s];
        }
    }
    __syncthreads();
    if (tid < 128) {
        float m = fmaxf(sred[0][tid][0], sred[0][tid][1]);
        float su = sred[1][tid][0] + sred[1][tid][1];
        g_sp[(b * HH + h) * LL + q0 + tid] = SCALE * m - SCALE * su * (1.0f / (float)LL);
    }
}

// ---------------- clear selection mask ----------------
__global__ void clear_kernel() {
    int i = blockIdx.x * 256 + threadIdx.x;
    if (i < BB * LL) g_selmask[i] = 0u;
}

// ---------------- top-40 per (b,h) ----------------
__global__ __launch_bounds__(256) void topk_kernel() {
    const int bh = blockIdx.x;
    const int b = bh >> 4, h = bh & 15;
    __shared__ float sp[LL];
    __shared__ float rv[8];
    __shared__ int ri[8];
    const int tid = threadIdx.x;
    for (int j = tid; j < LL; j += 256) sp[j] = g_sp[bh * LL + j];
    __syncthreads();
    for (int it = 0; it < TOPU; ++it) {
        float bv = -FLT_MAX; int bi = 1 << 30;
        for (int j = tid; j < LL; j += 256) {
            float v = sp[j];
            if (v > bv || (v == bv && j < bi)) { bv = v; bi = j; }
        }
#pragma unroll
        for (int o = 16; o > 0; o >>= 1) {
            float ov = __shfl_xor_sync(0xffffffffu, bv, o);
            int oi = __shfl_xor_sync(0xffffffffu, bi, o);
            if (ov > bv || (ov == bv && oi < bi)) { bv = ov; bi = oi; }
        }
        if ((tid & 31) == 0) { rv[tid >> 5] = bv; ri[tid >> 5] = bi; }
        __syncthreads();
        if (tid == 0) {
            float mv = -FLT_MAX; int mi = 1 << 30;
            for (int w = 0; w < 8; ++w)
                if (rv[w] > mv || (rv[w] == mv && ri[w] < mi)) { mv = rv[w]; mi = ri[w]; }
            g_topk[bh * TOPU + it] = mi;
            sp[mi] = -FLT_MAX;
            int row = b * LL + mi;
            atomicOr(&g_selmask[row], 1u << h);
            g_selu[row * HH + h] = it;
        }
        __syncthreads();
    }
}

// ---------------- attention over the top queries (AQ=4, round-7) --------------
__global__ __launch_bounds__(256) void attn_kernel() {
    const int b = blockIdx.z, h = blockIdx.y, ut = blockIdx.x;
    const int bh = b * HH + h;
    __shared__ float Qs[4][64];
    __shared__ float P[4][LL];
    __shared__ float red[4][8];
    __shared__ float gmx[4], gsm[4];
    __shared__ float cred[8][4][64];
    const float* __restrict__ gq = g_qkv[0];
    const float* __restrict__ gk = g_qkv[1];
    const float* __restrict__ gv = g_qkv[2];
    const int tid = threadIdx.x, lane = tid & 31, wp = tid >> 5;
    {
        int u = tid >> 6, d = tid & 63;
        int qi = g_topk[bh * TOPU + ut * 4 + u];
        Qs[u][d] = gq[((size_t)(b * LL + qi)) * DD + h * HD + d];
    }
    __syncthreads();
    const float* Kb = gk + (size_t)(b * LL) * DD + h * HD;
    float lm[4] = {-FLT_MAX, -FLT_MAX, -FLT_MAX, -FLT_MAX};
#pragma unroll
    for (int j = 0; j < 8; ++j) {
        int k = tid + 256 * j;
        const float4* kr = (const float4*)(Kb + (size_t)k * DD);
        float s[4] = {0.f, 0.f, 0.f, 0.f};
#pragma unroll
        for (int dv = 0; dv < 16; ++dv) {
            float4 kv = kr[dv];
#pragma unroll
            for (int u = 0; u < 4; ++u)
                s[u] += Qs[u][dv * 4 + 0] * kv.x + Qs[u][dv * 4 + 1] * kv.y +
                        Qs[u][dv * 4 + 2] * kv.z + Qs[u][dv * 4 + 3] * kv.w;
        }
#pragma unroll
        for (int u = 0; u < 4; ++u) {
            float sv = s[u] * SCALE;
            P[u][k] = sv;
            lm[u] = fmaxf(lm[u], sv);
        }
    }
#pragma unroll
    for (int u = 0; u < 4; ++u) {
#pragma unroll
        for (int o = 16; o > 0; o >>= 1) lm[u] = fmaxf(lm[u], __shfl_xor_sync(0xffffffffu, lm[u], o));
        if (lane == 0) red[u][wp] = lm[u];
    }
    __syncthreads();
    if (tid < 4) {
        float m = red[tid][0];
        for (int w = 1; w < 8; ++w) m = fmaxf(m, red[tid][w]);
        gmx[tid] = m;
    }
    __syncthreads();
    float ls[4] = {0.f, 0.f, 0.f, 0.f};
#pragma unroll
    for (int j = 0; j < 8; ++j) {
        int k = tid + 256 * j;
#pragma unroll
        for (int u = 0; u < 4; ++u) {
            float e = expf(P[u][k] - gmx[u]);
            P[u][k] = e;
            ls[u] += e;
        }
    }
#pragma unroll
    for (int u = 0; u < 4; ++u) {
#pragma unroll
        for (int o = 16; o > 0; o >>= 1) ls[u] += __shfl_xor_sync(0xffffffffu, ls[u], o);
        if (lane == 0) red[u][wp] = ls[u];
    }
    __syncthreads();
    if (tid < 4) {
        float s = 0.f;
        for (int w = 0; w < 8; ++w) s += red[tid][w];
        gsm[tid] = s;
    }
    __syncthreads();
    const float* Vb = gv + (size_t)(b * LL) * DD + h * HD;
    const int d0 = lane * 2;
    float c[4][2] = {{0.f,0.f},{0.f,0.f},{0.f,0.f},{0.f,0.f}};
    const int k0 = wp * 256;
    for (int kk = 0; kk < 256; ++kk) {
        int k = k0 + kk;
        float2 v = *(const float2*)(Vb + (size_t)k * DD + d0);
#pragma unroll
        for (int u = 0; u < 4; ++u) {
            float p = P[u][k];
            c[u][0] += p * v.x;
            c[u][1] += p * v.y;
        }
    }
#pragma unroll
    for (int u = 0; u < 4; ++u) {
        cred[wp][u][d0] = c[u][0];
        cred[wp][u][d0 + 1] = c[u][1];
    }
    __syncthreads();
    {
        int u = tid >> 6, d = tid & 63;
        float s = 0.f;
#pragma unroll
        for (int w = 0; w < 8; ++w) s += cred[w][u][d];
        g_ctx[((size_t)bh * TOPU + ut * 4 + u) * HD + d] = s / gsm[u];
    }
}

// ---------------- base = mean(V) over sequence ----------------
__global__ void base_kernel() {
    int b = blockIdx.y;
    int c = blockIdx.x * 256 + threadIdx.x;
    const float* p = g_qkv[2] + (size_t)b * LL * DD + c;
    float s = 0.f;
    for (int l = 0; l < LL; ++l) s += p[(size_t)l * DD];
    g_base[b * DD + c] = s * (1.0f / (float)LL);
}

// ---------------- base_out = base_row @ Wo^T + bo ----------------
__global__ __launch_bounds__(256) void baseout_kernel(const float* __restrict__ Wo,
                                                      const float* __restrict__ bo) {
    int b = blockIdx.y;
    int n = blockIdx.x * 256 + threadIdx.x;
    __shared__ float br[DD];
    for (int j = threadIdx.x; j < DD; j += 256) br[j] = g_base[b * DD + j];
    __syncthreads();
    const float4* wr = (const float4*)(Wo + (size_t)n * DD);
    const float4* b4 = (const float4*)br;
    float s = bo[n];
    for (int c = 0; c < DD / 4; ++c) {
        float4 w = wr[c], v = b4[c];
        s += w.x * v.x + w.y * v.y + w.z * v.z + w.w * v.w;
    }
    g_baseout[b * DD + n] = s;
}

// ---------------- final output ----------------
__global__ __launch_bounds__(256) void output_kernel(const float* __restrict__ Wo,
                                                     float* __restrict__ out) {
    const int row = blockIdx.x;
    const int b = row >> 11;
    const int tid = threadIdx.x;
    __shared__ float delta[HD];
    float o[4];
    *(float4*)o = *(const float4*)(g_baseout + b * DD + tid * 4);
    unsigned mask = g_selmask[row];
    while (mask) {
        int h = __ffs(mask) - 1;
        mask &= mask - 1;
        int u = g_selu[row * HH + h];
        if (tid < HD) {
            int bh = b * HH + h;
            delta[tid] = g_ctx[((size_t)bh * TOPU + u) * HD + tid] - g_base[b * DD + h * HD + tid];
        }
        __syncthreads();
        const float* wr = Wo + (size_t)tid * 4 * DD + h * HD;
#pragma unroll
        for (int j = 0; j < 4; ++j) {
            const float4* w4 = (const float4*)(wr + (size_t)j * DD);
            float s = 0.f;
#pragma unroll
            for (int d4 = 0; d4 < HD / 4; ++d4) {
                float4 w = w4[d4];
                s += w.x * delta[d4 * 4 + 0] + w.y * delta[d4 * 4 + 1] +
                     w.z * delta[d4 * 4 + 2] + w.w * delta[d4 * 4 + 3];
            }
            o[j] += s;
        }
        __syncthreads();
    }
    *(float4*)(out + (size_t)row * DD + tid * 4) = make_float4(o[0], o[1], o[2], o[3]);
}

// ---------------- launch ----------------
extern "C" void kernel_launch(void* const* d_in, const int* in_sizes, int n_in,
                              void* d_out, int out_size) {
    const float* query = (const float*)d_in[0];
    const float* key_t = (const float*)d_in[1];
    const float* value = (const float*)d_in[2];
    const float* Wq = (const float*)d_in[3];
    const float* bq = (const float*)d_in[4];
    const float* Wk = (const float*)d_in[5];
    const float* bk = (const float*)d_in[6];
    const float* Wv = (const float*)d_in[7];
    const float* bv = (const float*)d_in[8];
    const float* Wo = (const float*)d_in[9];
    const float* bo = (const float*)d_in[10];
    float* out = (float*)d_out;

    cudaFuncSetAttribute(proj_mma, cudaFuncAttributeMaxDynamicSharedMemorySize, PROJ_DSMEM);
    cudaFuncSetAttribute(sparsity_mma, cudaFuncAttributeMaxDynamicSharedMemorySize, SP_DSMEM);

    // launch order: sparsity_mma is the 5th launch; proj_mma 4th (ncu profiles #4)
    split_kernel<<<dim3(4096, 3), 256>>>(query, key_t, value, 0);     // 1: X planes
    split_kernel<<<dim3(1024, 3), 256>>>(Wq, Wk, Wv, 3);              // 2: W planes
    clear_kernel<<<(BB * LL + 255) / 256, 256>>>();                   // 3
    proj_mma<<<dim3(8, 32, 3), 256, PROJ_DSMEM>>>(bq, bk, bv);        // 4 (profiled)
    sparsity_mma<<<dim3(LL / 128, HH, BB), 512, SP_DSMEM>>>();        // 5
    topk_kernel<<<BB * HH, 256>>>();                                  // 6
    attn_kernel<<<dim3(TOPU / 4, HH, BB), 256>>>();                   // 7
    base_kernel<<<dim3(DD / 256, BB), 256>>>();                       // 8
    baseout_kernel<<<dim3(DD / 256, BB), 256>>>(Wo, bo);              // 9
    output_kernel<<<BB * LL, 256>>>(Wo, out);                         // 10
}

// round 13
// speedup vs baseline: 1.0989x; 1.0112x over previous
#include <cuda_runtime.h>
#include <cuda_bf16.h>
#include <math.h>
#include <float.h>
#include <stdint.h>

// Problem constants
#define BB 2
#define LL 2048
#define DD 1024
#define HH 16
#define HD 64
#define TOPU 40
#define MM (BB*LL)
#define SCALE 0.125f

// ---------------- scratch ----------------
__device__ float g_qkv[3][MM*DD];
__device__ __nv_bfloat16 g_xh[3][MM*DD];
__device__ __nv_bfloat16 g_xl[3][MM*DD];
__device__ __nv_bfloat16 g_wh[3][DD*DD];
__device__ __nv_bfloat16 g_wl[3][DD*DD];
__device__ __nv_bfloat16 g_qkh[2][MM*DD];   // bf16 planes of projected Q,K
__device__ __nv_bfloat16 g_qkl[2][MM*DD];
__device__ float g_sp[BB*HH*LL];
__device__ int g_topk[BB*HH*TOPU];
__device__ unsigned g_selmask[BB*LL];
__device__ int g_selu[BB*LL*HH];
__device__ float g_ctx[BB*HH*TOPU*HD];
__device__ float g_base[BB*DD];
__device__ float g_baseout[BB*DD];

// ---------------- helpers ----------------
__device__ __forceinline__ uint32_t smem_u32(const void* p) {
    uint32_t a;
    asm("{ .reg .u64 t; cvta.to.shared.u64 t, %1; cvt.u32.u64 %0, t; }" : "=r"(a) : "l"(p));
    return a;
}
__device__ __forceinline__ void ldsm4(uint32_t r[4], uint32_t addr) {
    asm volatile("ldmatrix.sync.aligned.m8n8.x4.shared.b16 {%0,%1,%2,%3}, [%4];"
        : "=r"(r[0]), "=r"(r[1]), "=r"(r[2]), "=r"(r[3]) : "r"(addr));
}
__device__ __forceinline__ void mma16816(float c[4], const uint32_t a[4], const uint32_t b[2]) {
    asm volatile("mma.sync.aligned.m16n8k16.row.col.f32.bf16.bf16.f32 "
        "{%0,%1,%2,%3},{%4,%5,%6,%7},{%8,%9},{%0,%1,%2,%3};"
        : "+f"(c[0]), "+f"(c[1]), "+f"(c[2]), "+f"(c[3])
        : "r"(a[0]), "r"(a[1]), "r"(a[2]), "r"(a[3]), "r"(b[0]), "r"(b[1]));
}
__device__ __forceinline__ void cpa16(uint32_t dst, const void* src) {
    asm volatile("cp.async.cg.shared.global [%0], [%1], 16;" :: "r"(dst), "l"(src) : "memory");
}
__device__ __forceinline__ void cpa_commit() {
    asm volatile("cp.async.commit_group;" ::: "memory");
}
template <int N> __device__ __forceinline__ void cpa_wait() {
    asm volatile("cp.async.wait_group %0;" :: "n"(N) : "memory");
}

// fp32x4 -> packed bf16 hi plane + lo plane (2-way split)
__device__ __forceinline__ void split_pack(float4 v, uint2& hi, uint2& lo) {
    __nv_bfloat16 bx = __float2bfloat16_rn(v.x);
    __nv_bfloat16 by = __float2bfloat16_rn(v.y);
    __nv_bfloat16 bz = __float2bfloat16_rn(v.z);
    __nv_bfloat16 bw = __float2bfloat16_rn(v.w);
    hi.x = ((uint32_t)__bfloat16_as_ushort(by) << 16) | __bfloat16_as_ushort(bx);
    hi.y = ((uint32_t)__bfloat16_as_ushort(bw) << 16) | __bfloat16_as_ushort(bz);
    __nv_bfloat16 lx = __float2bfloat16_rn(v.x - __bfloat162float(bx));
    __nv_bfloat16 ly = __float2bfloat16_rn(v.y - __bfloat162float(by));
    __nv_bfloat16 lz = __float2bfloat16_rn(v.z - __bfloat162float(bz));
    __nv_bfloat16 lw = __float2bfloat16_rn(v.w - __bfloat162float(bw));
    lo.x = ((uint32_t)__bfloat16_as_ushort(ly) << 16) | __bfloat16_as_ushort(lx);
    lo.y = ((uint32_t)__bfloat16_as_ushort(lw) << 16) | __bfloat16_as_ushort(lz);
}

// ================= split inputs: fp32 -> (hi, lo) bf16 planes =================
__global__ __launch_bounds__(256) void split_kernel(
    const float* __restrict__ s0, const float* __restrict__ s1, const float* __restrict__ s2,
    int base) {
    const int sid = base + blockIdx.y;
    const float* s = (blockIdx.y == 0) ? s0 : (blockIdx.y == 1) ? s1 : s2;
    __nv_bfloat16 *dh, *dl;
    int n4;
    if (sid < 3) { dh = g_xh[sid]; dl = g_xl[sid]; n4 = MM * DD / 4; }
    else         { dh = g_wh[sid - 3]; dl = g_wl[sid - 3]; n4 = DD * DD / 4; }
    int idx = blockIdx.x * 256 + threadIdx.x;
    if (idx >= n4) return;
    float4 val = ((const float4*)s)[idx];
    uint2 hi, lo;
    split_pack(val, hi, lo);
    ((uint2*)dh)[idx] = hi;
    ((uint2*)dl)[idx] = lo;
}

// ================= fused projections via cp.async + mma.sync ==================
// grid (8 ntiles, 32 mtiles, 3), 256 threads (8 warps, warp tile 32x64).
// SW64-swizzled 64B rows -> stage 32KB; 3 stages; (256,2) -> 2 blocks/SM.
#define PROJ_STG 32768
#define PROJ_DSMEM (3*PROJ_STG)

__global__ void __launch_bounds__(256, 2) proj_mma(
    const float* __restrict__ bi0, const float* __restrict__ bi1, const float* __restrict__ bi2) {
    extern __shared__ char sm[];
    const uint32_t sb = smem_u32(sm);
    const int z = blockIdx.z;
    const float* bias = (z == 0) ? bi0 : (z == 1) ? bi1 : bi2;
    float* __restrict__ Y = g_qkv[z];
    const int tid = threadIdx.x, lane = tid & 31, wid = tid >> 5;
    const int bm = blockIdx.y * 128, bn = blockIdx.x * 128;
    const int m0 = (wid >> 1) * 32, n0 = (wid & 1) * 64;

    float c[2][8][4];
#pragma unroll
    for (int i = 0; i < 2; ++i)
#pragma unroll
        for (int j = 0; j < 8; ++j)
#pragma unroll
            for (int k = 0; k < 4; ++k) c[i][j][k] = 0.f;

    const char* pXh[2]; const char* pXl[2]; const char* pWh[2]; const char* pWl[2];
    uint32_t doff[2];
#pragma unroll
    for (int i = 0; i < 2; ++i) {
        int idx = tid + 256 * i;
        int r = idx >> 2, seg = idx & 3;
        pXh[i] = (const char*)(g_xh[z] + (size_t)(bm + r) * DD + seg * 8);
        pXl[i] = (const char*)(g_xl[z] + (size_t)(bm + r) * DD + seg * 8);
        pWh[i] = (const char*)(g_wh[z] + (size_t)(bn + r) * DD + seg * 8);
        pWl[i] = (const char*)(g_wl[z] + (size_t)(bn + r) * DD + seg * 8);
        doff[i] = (uint32_t)r * 64 + (uint32_t)((seg ^ ((r >> 1) & 3)) << 4);
    }

    auto issue = [&](int kt) {
        uint32_t off = (uint32_t)kt * 64;
        uint32_t stg = sb + (uint32_t)(kt % 3) * PROJ_STG;
#pragma unroll
        for (int i = 0; i < 2; ++i) {
            uint32_t base = stg + doff[i];
            cpa16(base, pXh[i] + off);
            cpa16(base + 8192, pXl[i] + off);
            cpa16(base + 16384, pWh[i] + off);
            cpa16(base + 24576, pWl[i] + off);
        }
        cpa_commit();
    };

    const int hi16 = (lane >> 4) & 1;
    uint32_t aRB[2]; int aX[2];
#pragma unroll
    for (int i = 0; i < 2; ++i) {
        int r = m0 + (lane & 15) + i * 16;
        aRB[i] = (uint32_t)r * 64;
        aX[i] = (r >> 1) & 3;
    }
    uint32_t bRB[4]; int bX[4];
#pragma unroll
    for (int jh = 0; jh < 4; ++jh) {
        int r = n0 + jh * 16 + (lane & 15);
        bRB[jh] = (uint32_t)r * 64;
        bX[jh] = (r >> 1) & 3;
    }

    issue(0); issue(1);

#pragma unroll 1
    for (int kt = 0; kt < 32; ++kt) {
        if (kt < 31) cpa_wait<1>();
        else cpa_wait<0>();
        __syncthreads();
        if (kt + 2 < 32) issue(kt + 2);

        const uint32_t A = sb + (uint32_t)(kt % 3) * PROJ_STG;
#pragma unroll
        for (int s = 0; s < 2; ++s) {
            const int slot = s * 2 + hi16;
            uint32_t ah[2][4], al[2][4];
#pragma unroll
            for (int i = 0; i < 2; ++i) {
                uint32_t ao = aRB[i] + (uint32_t)((slot ^ aX[i]) << 4);
                ldsm4(ah[i], A + ao);
                ldsm4(al[i], A + 8192 + ao);
            }
#pragma unroll
            for (int jh = 0; jh < 4; ++jh) {
                uint32_t bo = bRB[jh] + (uint32_t)((slot ^ bX[jh]) << 4);
                uint32_t bh[2][2], bl[2][2];
                {
                    uint32_t q[4];
                    ldsm4(q, A + 16384 + bo);
                    bh[0][0] = q[0]; bh[0][1] = q[2]; bh[1][0] = q[1]; bh[1][1] = q[3];
                    ldsm4(q, A + 24576 + bo);
                    bl[0][0] = q[0]; bl[0][1] = q[2]; bl[1][0] = q[1]; bl[1][1] = q[3];
                }
#pragma unroll
                for (int i = 0; i < 2; ++i)
#pragma unroll
                    for (int jj = 0; jj < 2; ++jj) {
                        float* cc = c[i][jh * 2 + jj];
                        mma16816(cc, ah[i], bh[jj]);
                        mma16816(cc, ah[i], bl[jj]);
                        mma16816(cc, al[i], bh[jj]);
                    }
            }
        }
    }

    // epilogue: fragments -> fp32 Y (+bias); for Q,K also bf16 hi/lo planes
    __nv_bfloat16* qh = (z < 2) ? g_qkh[z] : 0;
    __nv_bfloat16* ql = (z < 2) ? g_qkl[z] : 0;
#pragma unroll
    for (int i = 0; i < 2; ++i) {
        int r0 = bm + m0 + i * 16 + (lane >> 2);
#pragma unroll
        for (int j = 0; j < 8; ++j) {
            int col = bn + n0 + j * 8 + (lane & 3) * 2;
            float bx = bias[col], by = bias[col + 1];
#pragma unroll
            for (int hh = 0; hh < 2; ++hh) {
                int rr = r0 + hh * 8;
                float v0 = c[i][j][hh * 2] + bx, v1 = c[i][j][hh * 2 + 1] + by;
                *(float2*)(Y + (size_t)rr * DD + col) = make_float2(v0, v1);
                if (z < 2) {
                    __nv_bfloat16 h0 = __float2bfloat16_rn(v0);
                    __nv_bfloat16 h1 = __float2bfloat16_rn(v1);
                    __nv_bfloat16 l0 = __float2bfloat16_rn(v0 - __bfloat162float(h0));
                    __nv_bfloat16 l1 = __float2bfloat16_rn(v1 - __bfloat162float(h1));
                    *(uint32_t*)(qh + (size_t)rr * DD + col) =
                        ((uint32_t)__bfloat16_as_ushort(h1) << 16) | __bfloat16_as_ushort(h0);
                    *(uint32_t*)(ql + (size_t)rr * DD + col) =
                        ((uint32_t)__bfloat16_as_ushort(l1) << 16) | __bfloat16_as_ushort(l0);
                }
            }
        }
    }
}

// ================= sparsity v2: Q frags hoisted, 16x64 warp tiles =============
// grid (16 qtiles, 16 h, 2 b), 256 thr (8 warps; warp tile 16 q-rows x 64 keys).
// Q (128x64) planes resident (36KB); K chunks of 64 keys, 2 stages x 18KB.
// (256,2) -> 2 blocks/SM with a 128-reg budget; Q fragments live in registers.
#define SPQ 18432
#define SPK0 36864
#define SPK_STG 18432
#define SP_DSMEM (SPK0 + 2*SPK_STG)

__global__ void __launch_bounds__(256, 2) sparsity_mma() {
    extern __shared__ char sm[];
    const uint32_t sb = smem_u32(sm);
    const int tid = threadIdx.x, lane = tid & 31, wid = tid >> 5;
    const int b = blockIdx.z, h = blockIdx.y, q0 = blockIdx.x * 128;
    const int m0 = wid * 16;
    const __nv_bfloat16* __restrict__ Qh = g_qkh[0];
    const __nv_bfloat16* __restrict__ Ql = g_qkl[0];
    const __nv_bfloat16* __restrict__ Kh = g_qkh[1];
    const __nv_bfloat16* __restrict__ Kl = g_qkl[1];

    auto issueK = [&](int kt) {
        uint32_t base = sb + SPK0 + (uint32_t)(kt & 1) * SPK_STG;
#pragma unroll
        for (int i = 0; i < 2; ++i) {
            int idx = tid + 256 * i;
            int r = idx >> 3, seg = idx & 7;
            uint32_t doff = (uint32_t)r * 144 + seg * 16;
            size_t src = (size_t)(b * LL + kt * 64 + r) * DD + h * HD + seg * 8;
            cpa16(base + doff, Kh + src);
            cpa16(base + 9216 + doff, Kl + src);
        }
        cpa_commit();
    };

    // prologue: Q planes + K chunk 0 in one group
    {
#pragma unroll
        for (int i = 0; i < 4; ++i) {
            int idx = tid + 256 * i;
            int r = idx >> 3, seg = idx & 7;
            uint32_t doff = (uint32_t)r * 144 + seg * 16;
            size_t src = (size_t)(b * LL + q0 + r) * DD + h * HD + seg * 8;
            cpa16(sb + doff, Qh + src);
            cpa16(sb + SPQ + doff, Ql + src);
        }
    }
    issueK(0);
    cpa_wait<0>();
    __syncthreads();

    // hoist Q fragments (constant across all K chunks): 4 k-steps x 2 planes
    uint32_t qa[4][2][4];
    {
        const uint32_t arow = sb + (uint32_t)(m0 + (lane & 15)) * 144 + ((lane & 16) ? 16 : 0);
#pragma unroll
        for (int s = 0; s < 4; ++s) {
            ldsm4(qa[s][0], arow + s * 32);
            ldsm4(qa[s][1], arow + SPQ + s * 32);
        }
    }

    uint32_t brow[4];
#pragma unroll
    for (int jh = 0; jh < 4; ++jh)
        brow[jh] = (uint32_t)(jh * 16 + (lane & 15)) * 144 + ((lane & 16) ? 16 : 0);

    float rmax[2] = {-FLT_MAX, -FLT_MAX}, rsum[2] = {0.f, 0.f};

#pragma unroll 1
    for (int kt = 0; kt < 32; ++kt) {
        if (kt + 1 < 32) issueK(kt + 1);
        const uint32_t K = sb + SPK0 + (uint32_t)(kt & 1) * SPK_STG;
        float c[4][2][4];
#pragma unroll
        for (int jh = 0; jh < 4; ++jh)
#pragma unroll
            for (int jj = 0; jj < 2; ++jj)
#pragma unroll
                for (int k = 0; k < 4; ++k) c[jh][jj][k] = 0.f;

#pragma unroll
        for (int s = 0; s < 4; ++s) {
            const uint32_t ko = s * 32;
#pragma unroll
            for (int jh = 0; jh < 4; ++jh) {
                uint32_t bh[2][2], bl[2][2];
                {
                    uint32_t q[4];
                    ldsm4(q, K + brow[jh] + ko);
                    bh[0][0] = q[0]; bh[0][1] = q[2]; bh[1][0] = q[1]; bh[1][1] = q[3];
                    ldsm4(q, K + 9216 + brow[jh] + ko);
                    bl[0][0] = q[0]; bl[0][1] = q[2]; bl[1][0] = q[1]; bl[1][1] = q[3];
                }
#pragma unroll
                for (int jj = 0; jj < 2; ++jj) {
                    float* cc = c[jh][jj];
                    mma16816(cc, qa[s][0], bh[jj]);
                    mma16816(cc, qa[s][0], bl[jj]);
                    mma16816(cc, qa[s][1], bh[jj]);
                }
            }
        }
        // fold scores into running max/sum (rows lane>>2 and +8)
#pragma unroll
        for (int jh = 0; jh < 4; ++jh)
#pragma unroll
            for (int jj = 0; jj < 2; ++jj) {
                float x0 = c[jh][jj][0], y0 = c[jh][jj][1];
                rmax[0] = fmaxf(rmax[0], fmaxf(x0, y0));
                rsum[0] += x0 + y0;
                float x1 = c[jh][jj][2], y1 = c[jh][jj][3];
                rmax[1] = fmaxf(rmax[1], fmaxf(x1, y1));
                rsum[1] += x1 + y1;
            }
        cpa_wait<0>();
        __syncthreads();
    }

    // reduce across quad lanes (different key columns, same row); write direct
#pragma unroll
    for (int s = 0; s < 2; ++s) {
        rmax[s] = fmaxf(rmax[s], __shfl_xor_sync(0xffffffffu, rmax[s], 1));
        rmax[s] = fmaxf(rmax[s], __shfl_xor_sync(0xffffffffu, rmax[s], 2));
        rsum[s] += __shfl_xor_sync(0xffffffffu, rsum[s], 1);
        rsum[s] += __shfl_xor_sync(0xffffffffu, rsum[s], 2);
    }
    if ((lane & 3) == 0) {
#pragma unroll
        for (int s = 0; s < 2; ++s) {
            int row = m0 + s * 8 + (lane >> 2);
            g_sp[(b * HH + h) * LL + q0 + row] =
                SCALE * rmax[s] - SCALE * rsum[s] * (1.0f / (float)LL);
        }
    }
}

// ---------------- clear selection mask ----------------
__global__ void clear_kernel() {
    int i = blockIdx.x * 256 + threadIdx.x;
    if (i < BB * LL) g_selmask[i] = 0u;
}

// ---------------- top-40 per (b,h) ----------------
__global__ __launch_bounds__(256) void topk_kernel() {
    const int bh = blockIdx.x;
    const int b = bh >> 4, h = bh & 15;
    __shared__ float sp[LL];
    __shared__ float rv[8];
    __shared__ int ri[8];
    const int tid = threadIdx.x;
    for (int j = tid; j < LL; j += 256) sp[j] = g_sp[bh * LL + j];
    __syncthreads();
    for (int it = 0; it < TOPU; ++it) {
        float bv = -FLT_MAX; int bi = 1 << 30;
        for (int j = tid; j < LL; j += 256) {
            float v = sp[j];
            if (v > bv || (v == bv && j < bi)) { bv = v; bi = j; }
        }
#pragma unroll
        for (int o = 16; o > 0; o >>= 1) {
            float ov = __shfl_xor_sync(0xffffffffu, bv, o);
            int oi = __shfl_xor_sync(0xffffffffu, bi, o);
            if (ov > bv || (ov == bv && oi < bi)) { bv = ov; bi = oi; }
        }
        if ((tid & 31) == 0) { rv[tid >> 5] = bv; ri[tid >> 5] = bi; }
        __syncthreads();
        if (tid == 0) {
            float mv = -FLT_MAX; int mi = 1 << 30;
            for (int w = 0; w < 8; ++w)
                if (rv[w] > mv || (rv[w] == mv && ri[w] < mi)) { mv = rv[w]; mi = ri[w]; }
            g_topk[bh * TOPU + it] = mi;
            sp[mi] = -FLT_MAX;
            int row = b * LL + mi;
            atomicOr(&g_selmask[row], 1u << h);
            g_selu[row * HH + h] = it;
        }
        __syncthreads();
    }
}

// ---------------- attention over the top queries (AQ=4) ----------------
__global__ __launch_bounds__(256) void attn_kernel() {
    const int b = blockIdx.z, h = blockIdx.y, ut = blockIdx.x;
    const int bh = b * HH + h;
    __shared__ float Qs[4][64];
    __shared__ float P[4][LL];
    __shared__ float red[4][8];
    __shared__ float gmx[4], gsm[4];
    __shared__ float cred[8][4][64];
    const float* __restrict__ gq = g_qkv[0];
    const float* __restrict__ gk = g_qkv[1];
    const float* __restrict__ gv = g_qkv[2];
    const int tid = threadIdx.x, lane = tid & 31, wp = tid >> 5;
    {
        int u = tid >> 6, d = tid & 63;
        int qi = g_topk[bh * TOPU + ut * 4 + u];
        Qs[u][d] = gq[((size_t)(b * LL + qi)) * DD + h * HD + d];
    }
    __syncthreads();
    const float* Kb = gk + (size_t)(b * LL) * DD + h * HD;
    float lm[4] = {-FLT_MAX, -FLT_MAX, -FLT_MAX, -FLT_MAX};
#pragma unroll
    for (int j = 0; j < 8; ++j) {
        int k = tid + 256 * j;
        const float4* kr = (const float4*)(Kb + (size_t)k * DD);
        float s[4] = {0.f, 0.f, 0.f, 0.f};
#pragma unroll
        for (int dv = 0; dv < 16; ++dv) {
            float4 kv = kr[dv];
#pragma unroll
            for (int u = 0; u < 4; ++u)
                s[u] += Qs[u][dv * 4 + 0] * kv.x + Qs[u][dv * 4 + 1] * kv.y +
                        Qs[u][dv * 4 + 2] * kv.z + Qs[u][dv * 4 + 3] * kv.w;
        }
#pragma unroll
        for (int u = 0; u < 4; ++u) {
            float sv = s[u] * SCALE;
            P[u][k] = sv;
            lm[u] = fmaxf(lm[u], sv);
        }
    }
#pragma unroll
    for (int u = 0; u < 4; ++u) {
#pragma unroll
        for (int o = 16; o > 0; o >>= 1) lm[u] = fmaxf(lm[u], __shfl_xor_sync(0xffffffffu, lm[u], o));
        if (lane == 0) red[u][wp] = lm[u];
    }
    __syncthreads();
    if (tid < 4) {
        float m = red[tid][0];
        for (int w = 1; w < 8; ++w) m = fmaxf(m, red[tid][w]);
        gmx[tid] = m;
    }
    __syncthreads();
    float ls[4] = {0.f, 0.f, 0.f, 0.f};
#pragma unroll
    for (int j = 0; j < 8; ++j) {
        int k = tid + 256 * j;
#pragma unroll
        for (int u = 0; u < 4; ++u) {
            float e = expf(P[u][k] - gmx[u]);
            P[u][k] = e;
            ls[u] += e;
        }
    }
#pragma unroll
    for (int u = 0; u < 4; ++u) {
#pragma unroll
        for (int o = 16; o > 0; o >>= 1) ls[u] += __shfl_xor_sync(0xffffffffu, ls[u], o);
        if (lane == 0) red[u][wp] = ls[u];
    }
    __syncthreads();
    if (tid < 4) {
        float s = 0.f;
        for (int w = 0; w < 8; ++w) s += red[tid][w];
        gsm[tid] = s;
    }
    __syncthreads();
    const float* Vb = gv + (size_t)(b * LL) * DD + h * HD;
    const int d0 = lane * 2;
    float c[4][2] = {{0.f,0.f},{0.f,0.f},{0.f,0.f},{0.f,0.f}};
    const int k0 = wp * 256;
    for (int kk = 0; kk < 256; ++kk) {
        int k = k0 + kk;
        float2 v = *(const float2*)(Vb + (size_t)k * DD + d0);
#pragma unroll
        for (int u = 0; u < 4; ++u) {
            float p = P[u][k];
            c[u][0] += p * v.x;
            c[u][1] += p * v.y;
        }
    }
#pragma unroll
    for (int u = 0; u < 4; ++u) {
        cred[wp][u][d0] = c[u][0];
        cred[wp][u][d0 + 1] = c[u][1];
    }
    __syncthreads();
    {
        int u = tid >> 6, d = tid & 63;
        float s = 0.f;
#pragma unroll
        for (int w = 0; w < 8; ++w) s += cred[w][u][d];
        g_ctx[((size_t)bh * TOPU + ut * 4 + u) * HD + d] = s / gsm[u];
    }
}

// ---------------- base = mean(V) over sequence ----------------
__global__ void base_kernel() {
    int b = blockIdx.y;
    int c = blockIdx.x * 256 + threadIdx.x;
    const float* p = g_qkv[2] + (size_t)b * LL * DD + c;
    float s = 0.f;
    for (int l = 0; l < LL; ++l) s += p[(size_t)l * DD];
    g_base[b * DD + c] = s * (1.0f / (float)LL);
}

// ---------------- base_out = base_row @ Wo^T + bo ----------------
__global__ __launch_bounds__(256) void baseout_kernel(const float* __restrict__ Wo,
                                                      const float* __restrict__ bo) {
    int b = blockIdx.y;
    int n = blockIdx.x * 256 + threadIdx.x;
    __shared__ float br[DD];
    for (int j = threadIdx.x; j < DD; j += 256) br[j] = g_base[b * DD + j];
    __syncthreads();
    const float4* wr = (const float4*)(Wo + (size_t)n * DD);
    const float4* b4 = (const float4*)br;
    float s = bo[n];
    for (int c = 0; c < DD / 4; ++c) {
        float4 w = wr[c], v = b4[c];
        s += w.x * v.x + w.y * v.y + w.z * v.z + w.w * v.w;
    }
    g_baseout[b * DD + n] = s;
}

// ---------------- final output ----------------
__global__ __launch_bounds__(256) void output_kernel(const float* __restrict__ Wo,
                                                     float* __restrict__ out) {
    const int row = blockIdx.x;
    const int b = row >> 11;
    const int tid = threadIdx.x;
    __shared__ float delta[HD];
    float o[4];
    *(float4*)o = *(const float4*)(g_baseout + b * DD + tid * 4);
    unsigned mask = g_selmask[row];
    while (mask) {
        int h = __ffs(mask) - 1;
        mask &= mask - 1;
        int u = g_selu[row * HH + h];
        if (tid < HD) {
            int bh = b * HH + h;
            delta[tid] = g_ctx[((size_t)bh * TOPU + u) * HD + tid] - g_base[b * DD + h * HD + tid];
        }
        __syncthreads();
        const float* wr = Wo + (size_t)tid * 4 * DD + h * HD;
#pragma unroll
        for (int j = 0; j < 4; ++j) {
            const float4* w4 = (const float4*)(wr + (size_t)j * DD);
            float s = 0.f;
#pragma unroll
            for (int d4 = 0; d4 < HD / 4; ++d4) {
                float4 w = w4[d4];
                s += w.x * delta[d4 * 4 + 0] + w.y * delta[d4 * 4 + 1] +
                     w.z * delta[d4 * 4 + 2] + w.w * delta[d4 * 4 + 3];
            }
            o[j] += s;
        }
        __syncthreads();
    }
    *(float4*)(out + (size_t)row * DD + tid * 4) = make_float4(o[0], o[1], o[2], o[3]);
}

// ---------------- launch ----------------
extern "C" void kernel_launch(void* const* d_in, const int* in_sizes, int n_in,
                              void* d_out, int out_size) {
    const float* query = (const float*)d_in[0];
    const float* key_t = (const float*)d_in[1];
    const float* value = (const float*)d_in[2];
    const float* Wq = (const float*)d_in[3];
    const float* bq = (const float*)d_in[4];
    const float* Wk = (const float*)d_in[5];
    const float* bk = (const float*)d_in[6];
    const float* Wv = (const float*)d_in[7];
    const float* bv = (const float*)d_in[8];
    const float* Wo = (const float*)d_in[9];
    const float* bo = (const float*)d_in[10];
    float* out = (float*)d_out;

    cudaFuncSetAttribute(proj_mma, cudaFuncAttributeMaxDynamicSharedMemorySize, PROJ_DSMEM);
    cudaFuncSetAttribute(sparsity_mma, cudaFuncAttributeMaxDynamicSharedMemorySize, SP_DSMEM);

    // launch order: clear 3rd so proj is 4th and sparsity 5th (ncu profiles #4)
    split_kernel<<<dim3(4096, 3), 256>>>(query, key_t, value, 0);     // 1: X planes
    split_kernel<<<dim3(1024, 3), 256>>>(Wq, Wk, Wv, 3);              // 2: W planes
    clear_kernel<<<(BB * LL + 255) / 256, 256>>>();                   // 3
    proj_mma<<<dim3(8, 32, 3), 256, PROJ_DSMEM>>>(bq, bk, bv);        // 4 (profiled)
    sparsity_mma<<<dim3(LL / 128, HH, BB), 256, SP_DSMEM>>>();        // 5
    topk_kernel<<<BB * HH, 256>>>();                                  // 6
    attn_kernel<<<dim3(TOPU / 4, HH, BB), 256>>>();                   // 7
    base_kernel<<<dim3(DD / 256, BB), 256>>>();                       // 8
    baseout_kernel<<<dim3(DD / 256, BB), 256>>>(Wo, bo);              // 9
    output_kernel<<<BB * LL, 256>>>(Wo, out);                         // 10
}

// round 14
// speedup vs baseline: 1.2512x; 1.1386x over previous
#include <cuda_runtime.h>
#include <cuda_bf16.h>
#include <math.h>
#include <float.h>
#include <stdint.h>

// Problem constants
#define BB 2
#define LL 2048
#define DD 1024
#define HH 16
#define HD 64
#define TOPU 40
#define MM (BB*LL)
#define SCALE 0.125f

// ---------------- scratch ----------------
__device__ float g_qkv[3][MM*DD];
__device__ __nv_bfloat16 g_xh[3][MM*DD];
__device__ __nv_bfloat16 g_xl[3][MM*DD];
__device__ __nv_bfloat16 g_wh[3][DD*DD];
__device__ __nv_bfloat16 g_wl[3][DD*DD];
__device__ __nv_bfloat16 g_qkh[2][MM*DD];   // bf16 planes of projected Q,K
__device__ __nv_bfloat16 g_qkl[2][MM*DD];
__device__ float g_sp[BB*HH*LL];
__device__ int g_topk[BB*HH*TOPU];
__device__ unsigned g_selmask[BB*LL];
__device__ int g_selu[BB*LL*HH];
__device__ float g_ctx[BB*HH*TOPU*HD];
__device__ float g_basepart[16][BB*DD];
__device__ float g_base[BB*DD];
__device__ float g_baseout[BB*DD];
__device__ float g_dout[BB*HH*TOPU*DD];     // per-(bh,u) output-space delta rows

// ---------------- helpers ----------------
__device__ __forceinline__ uint32_t smem_u32(const void* p) {
    uint32_t a;
    asm("{ .reg .u64 t; cvta.to.shared.u64 t, %1; cvt.u32.u64 %0, t; }" : "=r"(a) : "l"(p));
    return a;
}
__device__ __forceinline__ void ldsm4(uint32_t r[4], uint32_t addr) {
    asm volatile("ldmatrix.sync.aligned.m8n8.x4.shared.b16 {%0,%1,%2,%3}, [%4];"
        : "=r"(r[0]), "=r"(r[1]), "=r"(r[2]), "=r"(r[3]) : "r"(addr));
}
__device__ __forceinline__ void mma16816(float c[4], const uint32_t a[4], const uint32_t b[2]) {
    asm volatile("mma.sync.aligned.m16n8k16.row.col.f32.bf16.bf16.f32 "
        "{%0,%1,%2,%3},{%4,%5,%6,%7},{%8,%9},{%0,%1,%2,%3};"
        : "+f"(c[0]), "+f"(c[1]), "+f"(c[2]), "+f"(c[3])
        : "r"(a[0]), "r"(a[1]), "r"(a[2]), "r"(a[3]), "r"(b[0]), "r"(b[1]));
}
__device__ __forceinline__ void cpa16(uint32_t dst, const void* src) {
    asm volatile("cp.async.cg.shared.global [%0], [%1], 16;" :: "r"(dst), "l"(src) : "memory");
}
__device__ __forceinline__ void cpa_commit() {
    asm volatile("cp.async.commit_group;" ::: "memory");
}
template <int N> __device__ __forceinline__ void cpa_wait() {
    asm volatile("cp.async.wait_group %0;" :: "n"(N) : "memory");
}

// fp32x4 -> packed bf16 hi plane + lo plane (2-way split)
__device__ __forceinline__ void split_pack(float4 v, uint2& hi, uint2& lo) {
    __nv_bfloat16 bx = __float2bfloat16_rn(v.x);
    __nv_bfloat16 by = __float2bfloat16_rn(v.y);
    __nv_bfloat16 bz = __float2bfloat16_rn(v.z);
    __nv_bfloat16 bw = __float2bfloat16_rn(v.w);
    hi.x = ((uint32_t)__bfloat16_as_ushort(by) << 16) | __bfloat16_as_ushort(bx);
    hi.y = ((uint32_t)__bfloat16_as_ushort(bw) << 16) | __bfloat16_as_ushort(bz);
    __nv_bfloat16 lx = __float2bfloat16_rn(v.x - __bfloat162float(bx));
    __nv_bfloat16 ly = __float2bfloat16_rn(v.y - __bfloat162float(by));
    __nv_bfloat16 lz = __float2bfloat16_rn(v.z - __bfloat162float(bz));
    __nv_bfloat16 lw = __float2bfloat16_rn(v.w - __bfloat162float(bw));
    lo.x = ((uint32_t)__bfloat16_as_ushort(ly) << 16) | __bfloat16_as_ushort(lx);
    lo.y = ((uint32_t)__bfloat16_as_ushort(lw) << 16) | __bfloat16_as_ushort(lz);
}

// ================= split inputs: fp32 -> (hi, lo) bf16 planes =================
__global__ __launch_bounds__(256) void split_kernel(
    const float* __restrict__ s0, const float* __restrict__ s1, const float* __restrict__ s2,
    int base) {
    const int sid = base + blockIdx.y;
    const float* s = (blockIdx.y == 0) ? s0 : (blockIdx.y == 1) ? s1 : s2;
    __nv_bfloat16 *dh, *dl;
    int n4;
    if (sid < 3) { dh = g_xh[sid]; dl = g_xl[sid]; n4 = MM * DD / 4; }
    else         { dh = g_wh[sid - 3]; dl = g_wl[sid - 3]; n4 = DD * DD / 4; }
    int idx = blockIdx.x * 256 + threadIdx.x;
    if (idx >= n4) return;
    float4 val = ((const float4*)s)[idx];
    uint2 hi, lo;
    split_pack(val, hi, lo);
    ((uint2*)dh)[idx] = hi;
    ((uint2*)dl)[idx] = lo;
}

// ================= fused projections via cp.async + mma.sync ==================
#define PROJ_STG 32768
#define PROJ_DSMEM (3*PROJ_STG)

__global__ void __launch_bounds__(256, 2) proj_mma(
    const float* __restrict__ bi0, const float* __restrict__ bi1, const float* __restrict__ bi2) {
    extern __shared__ char sm[];
    const uint32_t sb = smem_u32(sm);
    const int z = blockIdx.z;
    const float* bias = (z == 0) ? bi0 : (z == 1) ? bi1 : bi2;
    float* __restrict__ Y = g_qkv[z];
    const int tid = threadIdx.x, lane = tid & 31, wid = tid >> 5;
    const int bm = blockIdx.y * 128, bn = blockIdx.x * 128;
    const int m0 = (wid >> 1) * 32, n0 = (wid & 1) * 64;

    float c[2][8][4];
#pragma unroll
    for (int i = 0; i < 2; ++i)
#pragma unroll
        for (int j = 0; j < 8; ++j)
#pragma unroll
            for (int k = 0; k < 4; ++k) c[i][j][k] = 0.f;

    const char* pXh[2]; const char* pXl[2]; const char* pWh[2]; const char* pWl[2];
    uint32_t doff[2];
#pragma unroll
    for (int i = 0; i < 2; ++i) {
        int idx = tid + 256 * i;
        int r = idx >> 2, seg = idx & 3;
        pXh[i] = (const char*)(g_xh[z] + (size_t)(bm + r) * DD + seg * 8);
        pXl[i] = (const char*)(g_xl[z] + (size_t)(bm + r) * DD + seg * 8);
        pWh[i] = (const char*)(g_wh[z] + (size_t)(bn + r) * DD + seg * 8);
        pWl[i] = (const char*)(g_wl[z] + (size_t)(bn + r) * DD + seg * 8);
        doff[i] = (uint32_t)r * 64 + (uint32_t)((seg ^ ((r >> 1) & 3)) << 4);
    }

    auto issue = [&](int kt) {
        uint32_t off = (uint32_t)kt * 64;
        uint32_t stg = sb + (uint32_t)(kt % 3) * PROJ_STG;
#pragma unroll
        for (int i = 0; i < 2; ++i) {
            uint32_t base = stg + doff[i];
            cpa16(base, pXh[i] + off);
            cpa16(base + 8192, pXl[i] + off);
            cpa16(base + 16384, pWh[i] + off);
            cpa16(base + 24576, pWl[i] + off);
        }
        cpa_commit();
    };

    const int hi16 = (lane >> 4) & 1;
    uint32_t aRB[2]; int aX[2];
#pragma unroll
    for (int i = 0; i < 2; ++i) {
        int r = m0 + (lane & 15) + i * 16;
        aRB[i] = (uint32_t)r * 64;
        aX[i] = (r >> 1) & 3;
    }
    uint32_t bRB[4]; int bX[4];
#pragma unroll
    for (int jh = 0; jh < 4; ++jh) {
        int r = n0 + jh * 16 + (lane & 15);
        bRB[jh] = (uint32_t)r * 64;
        bX[jh] = (r >> 1) & 3;
    }

    issue(0); issue(1);

#pragma unroll 1
    for (int kt = 0; kt < 32; ++kt) {
        if (kt < 31) cpa_wait<1>();
        else cpa_wait<0>();
        __syncthreads();
        if (kt + 2 < 32) issue(kt + 2);

        const uint32_t A = sb + (uint32_t)(kt % 3) * PROJ_STG;
#pragma unroll
        for (int s = 0; s < 2; ++s) {
            const int slot = s * 2 + hi16;
            uint32_t ah[2][4], al[2][4];
#pragma unroll
            for (int i = 0; i < 2; ++i) {
                uint32_t ao = aRB[i] + (uint32_t)((slot ^ aX[i]) << 4);
                ldsm4(ah[i], A + ao);
                ldsm4(al[i], A + 8192 + ao);
            }
#pragma unroll
            for (int jh = 0; jh < 4; ++jh) {
                uint32_t bo = bRB[jh] + (uint32_t)((slot ^ bX[jh]) << 4);
                uint32_t bh[2][2], bl[2][2];
                {
                    uint32_t q[4];
                    ldsm4(q, A + 16384 + bo);
                    bh[0][0] = q[0]; bh[0][1] = q[2]; bh[1][0] = q[1]; bh[1][1] = q[3];
                    ldsm4(q, A + 24576 + bo);
                    bl[0][0] = q[0]; bl[0][1] = q[2]; bl[1][0] = q[1]; bl[1][1] = q[3];
                }
#pragma unroll
                for (int i = 0; i < 2; ++i)
#pragma unroll
                    for (int jj = 0; jj < 2; ++jj) {
                        float* cc = c[i][jh * 2 + jj];
                        mma16816(cc, ah[i], bh[jj]);
                        mma16816(cc, ah[i], bl[jj]);
                        mma16816(cc, al[i], bh[jj]);
                    }
            }
        }
    }

    // epilogue
    __nv_bfloat16* qh = (z < 2) ? g_qkh[z] : 0;
    __nv_bfloat16* ql = (z < 2) ? g_qkl[z] : 0;
#pragma unroll
    for (int i = 0; i < 2; ++i) {
        int r0 = bm + m0 + i * 16 + (lane >> 2);
#pragma unroll
        for (int j = 0; j < 8; ++j) {
            int col = bn + n0 + j * 8 + (lane & 3) * 2;
            float bx = bias[col], by = bias[col + 1];
#pragma unroll
            for (int hh = 0; hh < 2; ++hh) {
                int rr = r0 + hh * 8;
                float v0 = c[i][j][hh * 2] + bx, v1 = c[i][j][hh * 2 + 1] + by;
                *(float2*)(Y + (size_t)rr * DD + col) = make_float2(v0, v1);
                if (z < 2) {
                    __nv_bfloat16 h0 = __float2bfloat16_rn(v0);
                    __nv_bfloat16 h1 = __float2bfloat16_rn(v1);
                    __nv_bfloat16 l0 = __float2bfloat16_rn(v0 - __bfloat162float(h0));
                    __nv_bfloat16 l1 = __float2bfloat16_rn(v1 - __bfloat162float(h1));
                    *(uint32_t*)(qh + (size_t)rr * DD + col) =
                        ((uint32_t)__bfloat16_as_ushort(h1) << 16) | __bfloat16_as_ushort(h0);
                    *(uint32_t*)(ql + (size_t)rr * DD + col) =
                        ((uint32_t)__bfloat16_as_ushort(l1) << 16) | __bfloat16_as_ushort(l0);
                }
            }
        }
    }
}

// ================= sparsity v2 (round-13) =====================================
#define SPQ 18432
#define SPK0 36864
#define SPK_STG 18432
#define SP_DSMEM (SPK0 + 2*SPK_STG)

__global__ void __launch_bounds__(256, 2) sparsity_mma() {
    extern __shared__ char sm[];
    const uint32_t sb = smem_u32(sm);
    const int tid = threadIdx.x, lane = tid & 31, wid = tid >> 5;
    const int b = blockIdx.z, h = blockIdx.y, q0 = blockIdx.x * 128;
    const int m0 = wid * 16;
    const __nv_bfloat16* __restrict__ Qh = g_qkh[0];
    const __nv_bfloat16* __restrict__ Ql = g_qkl[0];
    const __nv_bfloat16* __restrict__ Kh = g_qkh[1];
    const __nv_bfloat16* __restrict__ Kl = g_qkl[1];

    auto issueK = [&](int kt) {
        uint32_t base = sb + SPK0 + (uint32_t)(kt & 1) * SPK_STG;
#pragma unroll
        for (int i = 0; i < 2; ++i) {
            int idx = tid + 256 * i;
            int r = idx >> 3, seg = idx & 7;
            uint32_t doff = (uint32_t)r * 144 + seg * 16;
            size_t src = (size_t)(b * LL + kt * 64 + r) * DD + h * HD + seg * 8;
            cpa16(base + doff, Kh + src);
            cpa16(base + 9216 + doff, Kl + src);
        }
        cpa_commit();
    };

    {
#pragma unroll
        for (int i = 0; i < 4; ++i) {
            int idx = tid + 256 * i;
            int r = idx >> 3, seg = idx & 7;
            uint32_t doff = (uint32_t)r * 144 + seg * 16;
            size_t src = (size_t)(b * LL + q0 + r) * DD + h * HD + seg * 8;
            cpa16(sb + doff, Qh + src);
            cpa16(sb + SPQ + doff, Ql + src);
        }
    }
    issueK(0);
    cpa_wait<0>();
    __syncthreads();

    uint32_t qa[4][2][4];
    {
        const uint32_t arow = sb + (uint32_t)(m0 + (lane & 15)) * 144 + ((lane & 16) ? 16 : 0);
#pragma unroll
        for (int s = 0; s < 4; ++s) {
            ldsm4(qa[s][0], arow + s * 32);
            ldsm4(qa[s][1], arow + SPQ + s * 32);
        }
    }

    uint32_t brow[4];
#pragma unroll
    for (int jh = 0; jh < 4; ++jh)
        brow[jh] = (uint32_t)(jh * 16 + (lane & 15)) * 144 + ((lane & 16) ? 16 : 0);

    float rmax[2] = {-FLT_MAX, -FLT_MAX}, rsum[2] = {0.f, 0.f};

#pragma unroll 1
    for (int kt = 0; kt < 32; ++kt) {
        if (kt + 1 < 32) issueK(kt + 1);
        const uint32_t K = sb + SPK0 + (uint32_t)(kt & 1) * SPK_STG;
        float c[4][2][4];
#pragma unroll
        for (int jh = 0; jh < 4; ++jh)
#pragma unroll
            for (int jj = 0; jj < 2; ++jj)
#pragma unroll
                for (int k = 0; k < 4; ++k) c[jh][jj][k] = 0.f;

#pragma unroll
        for (int s = 0; s < 4; ++s) {
            const uint32_t ko = s * 32;
#pragma unroll
            for (int jh = 0; jh < 4; ++jh) {
                uint32_t bh[2][2], bl[2][2];
                {
                    uint32_t q[4];
                    ldsm4(q, K + brow[jh] + ko);
                    bh[0][0] = q[0]; bh[0][1] = q[2]; bh[1][0] = q[1]; bh[1][1] = q[3];
                    ldsm4(q, K + 9216 + brow[jh] + ko);
                    bl[0][0] = q[0]; bl[0][1] = q[2]; bl[1][0] = q[1]; bl[1][1] = q[3];
                }
#pragma unroll
                for (int jj = 0; jj < 2; ++jj) {
                    float* cc = c[jh][jj];
                    mma16816(cc, qa[s][0], bh[jj]);
                    mma16816(cc, qa[s][0], bl[jj]);
                    mma16816(cc, qa[s][1], bh[jj]);
                }
            }
        }
#pragma unroll
        for (int jh = 0; jh < 4; ++jh)
#pragma unroll
            for (int jj = 0; jj < 2; ++jj) {
                float x0 = c[jh][jj][0], y0 = c[jh][jj][1];
                rmax[0] = fmaxf(rmax[0], fmaxf(x0, y0));
                rsum[0] += x0 + y0;
                float x1 = c[jh][jj][2], y1 = c[jh][jj][3];
                rmax[1] = fmaxf(rmax[1], fmaxf(x1, y1));
                rsum[1] += x1 + y1;
            }
        cpa_wait<0>();
        __syncthreads();
    }

#pragma unroll
    for (int s = 0; s < 2; ++s) {
        rmax[s] = fmaxf(rmax[s], __shfl_xor_sync(0xffffffffu, rmax[s], 1));
        rmax[s] = fmaxf(rmax[s], __shfl_xor_sync(0xffffffffu, rmax[s], 2));
        rsum[s] += __shfl_xor_sync(0xffffffffu, rsum[s], 1);
        rsum[s] += __shfl_xor_sync(0xffffffffu, rsum[s], 2);
    }
    if ((lane & 3) == 0) {
#pragma unroll
        for (int s = 0; s < 2; ++s) {
            int row = m0 + s * 8 + (lane >> 2);
            g_sp[(b * HH + h) * LL + q0 + row] =
                SCALE * rmax[s] - SCALE * rsum[s] * (1.0f / (float)LL);
        }
    }
}

// ---------------- clear selection mask ----------------
__global__ void clear_kernel() {
    int i = blockIdx.x * 256 + threadIdx.x;
    if (i < BB * LL) g_selmask[i] = 0u;
}

// ---------------- top-40 per (b,h) ----------------
__global__ __launch_bounds__(256) void topk_kernel() {
    const int bh = blockIdx.x;
    const int b = bh >> 4, h = bh & 15;
    __shared__ float sp[LL];
    __shared__ float rv[8];
    __shared__ int ri[8];
    const int tid = threadIdx.x;
    for (int j = tid; j < LL; j += 256) sp[j] = g_sp[bh * LL + j];
    __syncthreads();
    for (int it = 0; it < TOPU; ++it) {
        float bv = -FLT_MAX; int bi = 1 << 30;
        for (int j = tid; j < LL; j += 256) {
            float v = sp[j];
            if (v > bv || (v == bv && j < bi)) { bv = v; bi = j; }
        }
#pragma unroll
        for (int o = 16; o > 0; o >>= 1) {
            float ov = __shfl_xor_sync(0xffffffffu, bv, o);
            int oi = __shfl_xor_sync(0xffffffffu, bi, o);
            if (ov > bv || (ov == bv && oi < bi)) { bv = ov; bi = oi; }
        }
        if ((tid & 31) == 0) { rv[tid >> 5] = bv; ri[tid >> 5] = bi; }
        __syncthreads();
        if (tid == 0) {
            float mv = -FLT_MAX; int mi = 1 << 30;
            for (int w = 0; w < 8; ++w)
                if (rv[w] > mv || (rv[w] == mv && ri[w] < mi)) { mv = rv[w]; mi = ri[w]; }
            g_topk[bh * TOPU + it] = mi;
            sp[mi] = -FLT_MAX;
            int row = b * LL + mi;
            atomicOr(&g_selmask[row], 1u << h);
            g_selu[row * HH + h] = it;
        }
        __syncthreads();
    }
}

// ---------------- attention over the top queries (AQ=4) ----------------
__global__ __launch_bounds__(256) void attn_kernel() {
    const int b = blockIdx.z, h = blockIdx.y, ut = blockIdx.x;
    const int bh = b * HH + h;
    __shared__ float Qs[4][64];
    __shared__ float P[4][LL];
    __shared__ float red[4][8];
    __shared__ float gmx[4], gsm[4];
    __shared__ float cred[8][4][64];
    const float* __restrict__ gq = g_qkv[0];
    const float* __restrict__ gk = g_qkv[1];
    const float* __restrict__ gv = g_qkv[2];
    const int tid = threadIdx.x, lane = tid & 31, wp = tid >> 5;
    {
        int u = tid >> 6, d = tid & 63;
        int qi = g_topk[bh * TOPU + ut * 4 + u];
        Qs[u][d] = gq[((size_t)(b * LL + qi)) * DD + h * HD + d];
    }
    __syncthreads();
    const float* Kb = gk + (size_t)(b * LL) * DD + h * HD;
    float lm[4] = {-FLT_MAX, -FLT_MAX, -FLT_MAX, -FLT_MAX};
#pragma unroll
    for (int j = 0; j < 8; ++j) {
        int k = tid + 256 * j;
        const float4* kr = (const float4*)(Kb + (size_t)k * DD);
        float s[4] = {0.f, 0.f, 0.f, 0.f};
#pragma unroll
        for (int dv = 0; dv < 16; ++dv) {
            float4 kv = kr[dv];
#pragma unroll
            for (int u = 0; u < 4; ++u)
                s[u] += Qs[u][dv * 4 + 0] * kv.x + Qs[u][dv * 4 + 1] * kv.y +
                        Qs[u][dv * 4 + 2] * kv.z + Qs[u][dv * 4 + 3] * kv.w;
        }
#pragma unroll
        for (int u = 0; u < 4; ++u) {
            float sv = s[u] * SCALE;
            P[u][k] = sv;
            lm[u] = fmaxf(lm[u], sv);
        }
    }
#pragma unroll
    for (int u = 0; u < 4; ++u) {
#pragma unroll
        for (int o = 16; o > 0; o >>= 1) lm[u] = fmaxf(lm[u], __shfl_xor_sync(0xffffffffu, lm[u], o));
        if (lane == 0) red[u][wp] = lm[u];
    }
    __syncthreads();
    if (tid < 4) {
        float m = red[tid][0];
        for (int w = 1; w < 8; ++w) m = fmaxf(m, red[tid][w]);
        gmx[tid] = m;
    }
    __syncthreads();
    float ls[4] = {0.f, 0.f, 0.f, 0.f};
#pragma unroll
    for (int j = 0; j < 8; ++j) {
        int k = tid + 256 * j;
#pragma unroll
        for (int u = 0; u < 4; ++u) {
            float e = expf(P[u][k] - gmx[u]);
            P[u][k] = e;
            ls[u] += e;
        }
    }
#pragma unroll
    for (int u = 0; u < 4; ++u) {
#pragma unroll
        for (int o = 16; o > 0; o >>= 1) ls[u] += __shfl_xor_sync(0xffffffffu, ls[u], o);
        if (lane == 0) red[u][wp] = ls[u];
    }
    __syncthreads();
    if (tid < 4) {
        float s = 0.f;
        for (int w = 0; w < 8; ++w) s += red[tid][w];
        gsm[tid] = s;
    }
    __syncthreads();
    const float* Vb = gv + (size_t)(b * LL) * DD + h * HD;
    const int d0 = lane * 2;
    float c[4][2] = {{0.f,0.f},{0.f,0.f},{0.f,0.f},{0.f,0.f}};
    const int k0 = wp * 256;
    for (int kk = 0; kk < 256; ++kk) {
        int k = k0 + kk;
        float2 v = *(const float2*)(Vb + (size_t)k * DD + d0);
#pragma unroll
        for (int u = 0; u < 4; ++u) {
            float p = P[u][k];
            c[u][0] += p * v.x;
            c[u][1] += p * v.y;
        }
    }
#pragma unroll
    for (int u = 0; u < 4; ++u) {
        cred[wp][u][d0] = c[u][0];
        cred[wp][u][d0 + 1] = c[u][1];
    }
    __syncthreads();
    {
        int u = tid >> 6, d = tid & 63;
        float s = 0.f;
#pragma unroll
        for (int w = 0; w < 8; ++w) s += cred[w][u][d];
        g_ctx[((size_t)bh * TOPU + ut * 4 + u) * HD + d] = s / gsm[u];
    }
}

// ---------------- base mean: two-stage deterministic reduction ----------------
__global__ void base_part() {
    int b = blockIdx.y, seg = blockIdx.z;
    int c = blockIdx.x * 256 + threadIdx.x;
    const float* p = g_qkv[2] + (size_t)b * LL * DD + (size_t)seg * 128 * DD + c;
    float s = 0.f;
#pragma unroll 4
    for (int l = 0; l < 128; ++l) s += p[(size_t)l * DD];
    g_basepart[seg][b * DD + c] = s;
}
__global__ void base_fin() {
    int i = blockIdx.x * 256 + threadIdx.x;
    float s = 0.f;
#pragma unroll
    for (int seg = 0; seg < 16; ++seg) s += g_basepart[seg][i];
    g_base[i] = s * (1.0f / (float)LL);
}

// ---------------- base_out = base_row @ Wo^T + bo ----------------
__global__ __launch_bounds__(256) void baseout_kernel(const float* __restrict__ Wo,
                                                      const float* __restrict__ bo) {
    int b = blockIdx.y;
    int n = blockIdx.x * 256 + threadIdx.x;
    __shared__ float br[DD];
    for (int j = threadIdx.x; j < DD; j += 256) br[j] = g_base[b * DD + j];
    __syncthreads();
    const float4* wr = (const float4*)(Wo + (size_t)n * DD);
    const float4* b4 = (const float4*)br;
    float s = bo[n];
    for (int c = 0; c < DD / 4; ++c) {
        float4 w = wr[c], v = b4[c];
        s += w.x * v.x + w.y * v.y + w.z * v.z + w.w * v.w;
    }
    g_baseout[b * DD + n] = s;
}

// ---------------- deltaout: (ctx - base) @ Wo_slice^T per (bh, u) -------------
// grid 32 (bh), 256 threads. smem: delta[40][64] + Wo tile [256][65] (padded).
#define DO_DSMEM ((40*64 + 256*65) * 4)

__global__ __launch_bounds__(256) void deltaout_kernel(const float* __restrict__ Wo) {
    extern __shared__ float dsm[];
    float* sdelta = dsm;               // [40][64]
    float* tile = dsm + 40 * 64;       // [256][65]
    const int bh = blockIdx.x;
    const int b = bh >> 4, h = bh & 15;
    const int tid = threadIdx.x;

    for (int idx = tid; idx < TOPU * HD; idx += 256) {
        int u = idx >> 6, d = idx & 63;
        sdelta[idx] = g_ctx[((size_t)bh * TOPU + u) * HD + d] - g_base[b * DD + h * HD + d];
    }
    __syncthreads();

#pragma unroll 1
    for (int t = 0; t < 4; ++t) {
        const int n0 = t * 256;
        // coalesced tile load: 256 rows x 64 cols
#pragma unroll
        for (int i = 0; i < 32; ++i) {
            int idx = tid + 256 * i;
            int r = idx >> 5, c2 = idx & 31;
            float2 v = *(const float2*)(Wo + (size_t)(n0 + r) * DD + h * HD + c2 * 2);
            tile[r * 65 + c2 * 2] = v.x;
            tile[r * 65 + c2 * 2 + 1] = v.y;
        }
        __syncthreads();
        float acc[TOPU];
#pragma unroll
        for (int u = 0; u < TOPU; ++u) acc[u] = 0.f;
#pragma unroll 8
        for (int d = 0; d < HD; ++d) {
            float td = tile[tid * 65 + d];
#pragma unroll
            for (int u = 0; u < TOPU; ++u) acc[u] += td * sdelta[u * 64 + d];
        }
#pragma unroll
        for (int u = 0; u < TOPU; ++u)
            g_dout[((size_t)bh * TOPU + u) * DD + n0 + tid] = acc[u];
        __syncthreads();
    }
}

// ---------------- final output: stream baseout + selected deltaout rows -------
__global__ __launch_bounds__(256) void output_kernel(float* __restrict__ out) {
    const int row = blockIdx.x;
    const int b = row >> 11;
    const int tid = threadIdx.x;
    float4 o = *(const float4*)(g_baseout + b * DD + tid * 4);
    unsigned mask = g_selmask[row];
    while (mask) {
        int h = __ffs(mask) - 1;
        mask &= mask - 1;
        int u = g_selu[row * HH + h];
        int bh = b * HH + h;
        float4 d = *(const float4*)(g_dout + ((size_t)bh * TOPU + u) * DD + tid * 4);
        o.x += d.x; o.y += d.y; o.z += d.z; o.w += d.w;
    }
    *(float4*)(out + (size_t)row * DD + tid * 4) = o;
}

// ---------------- launch ----------------
extern "C" void kernel_launch(void* const* d_in, const int* in_sizes, int n_in,
                              void* d_out, int out_size) {
    const float* query = (const float*)d_in[0];
    const float* key_t = (const float*)d_in[1];
    const float* value = (const float*)d_in[2];
    const float* Wq = (const float*)d_in[3];
    const float* bq = (const float*)d_in[4];
    const float* Wk = (const float*)d_in[5];
    const float* bk = (const float*)d_in[6];
    const float* Wv = (const float*)d_in[7];
    const float* bv = (const float*)d_in[8];
    const float* Wo = (const float*)d_in[9];
    const float* bo = (const float*)d_in[10];
    float* out = (float*)d_out;

    cudaFuncSetAttribute(proj_mma, cudaFuncAttributeMaxDynamicSharedMemorySize, PROJ_DSMEM);
    cudaFuncSetAttribute(sparsity_mma, cudaFuncAttributeMaxDynamicSharedMemorySize, SP_DSMEM);
    cudaFuncSetAttribute(deltaout_kernel, cudaFuncAttributeMaxDynamicSharedMemorySize, DO_DSMEM);

    split_kernel<<<dim3(4096, 3), 256>>>(query, key_t, value, 0);     // 1
    split_kernel<<<dim3(1024, 3), 256>>>(Wq, Wk, Wv, 3);              // 2
    clear_kernel<<<(BB * LL + 255) / 256, 256>>>();                   // 3
    proj_mma<<<dim3(8, 32, 3), 256, PROJ_DSMEM>>>(bq, bk, bv);        // 4 (profiled)
    sparsity_mma<<<dim3(LL / 128, HH, BB), 256, SP_DSMEM>>>();        // 5
    topk_kernel<<<BB * HH, 256>>>();                                  // 6
    attn_kernel<<<dim3(TOPU / 4, HH, BB), 256>>>();                   // 7
    base_part<<<dim3(DD / 256, BB, 16), 256>>>();                     // 8
    base_fin<<<BB * DD / 256, 256>>>();                               // 9
    baseout_kernel<<<dim3(DD / 256, BB), 256>>>(Wo, bo);              // 10
    deltaout_kernel<<<BB * HH, 256, DO_DSMEM>>>(Wo);                  // 11
    output_kernel<<<BB * LL, 256>>>(out);                             // 12
}

// round 15
// speedup vs baseline: 1.2790x; 1.0222x over previous
#include <cuda_runtime.h>
#include <cuda_bf16.h>
#include <math.h>
#include <float.h>
#include <stdint.h>

// Problem constants
#define BB 2
#define LL 2048
#define DD 1024
#define HH 16
#define HD 64
#define TOPU 40
#define MM (BB*LL)
#define SCALE 0.125f

// ---------------- scratch ----------------
__device__ float g_qkv[3][MM*DD];
__device__ __nv_bfloat16 g_xh[3][MM*DD];
__device__ __nv_bfloat16 g_xl[3][MM*DD];
__device__ __nv_bfloat16 g_wh[3][DD*DD];
__device__ __nv_bfloat16 g_wl[3][DD*DD];
__device__ __nv_bfloat16 g_qkh[2][MM*DD];   // bf16 planes of projected Q,K
__device__ __nv_bfloat16 g_qkl[2][MM*DD];
__device__ float g_sp[BB*HH*LL];
__device__ int g_topk[BB*HH*TOPU];
__device__ unsigned g_selmask[BB*LL];
__device__ int g_selu[BB*LL*HH];
__device__ float g_ctx[BB*HH*TOPU*HD];
__device__ float g_basepart[16][BB*DD];
__device__ float g_base[BB*DD];
__device__ float g_baseout[BB*DD];
__device__ float g_dout[BB*HH*TOPU*DD];     // per-(bh,u) output-space delta rows

// ---------------- helpers ----------------
__device__ __forceinline__ uint32_t smem_u32(const void* p) {
    uint32_t a;
    asm("{ .reg .u64 t; cvta.to.shared.u64 t, %1; cvt.u32.u64 %0, t; }" : "=r"(a) : "l"(p));
    return a;
}
__device__ __forceinline__ void ldsm4(uint32_t r[4], uint32_t addr) {
    asm volatile("ldmatrix.sync.aligned.m8n8.x4.shared.b16 {%0,%1,%2,%3}, [%4];"
        : "=r"(r[0]), "=r"(r[1]), "=r"(r[2]), "=r"(r[3]) : "r"(addr));
}
__device__ __forceinline__ void mma16816(float c[4], const uint32_t a[4], const uint32_t b[2]) {
    asm volatile("mma.sync.aligned.m16n8k16.row.col.f32.bf16.bf16.f32 "
        "{%0,%1,%2,%3},{%4,%5,%6,%7},{%8,%9},{%0,%1,%2,%3};"
        : "+f"(c[0]), "+f"(c[1]), "+f"(c[2]), "+f"(c[3])
        : "r"(a[0]), "r"(a[1]), "r"(a[2]), "r"(a[3]), "r"(b[0]), "r"(b[1]));
}
__device__ __forceinline__ void cpa16(uint32_t dst, const void* src) {
    asm volatile("cp.async.cg.shared.global [%0], [%1], 16;" :: "r"(dst), "l"(src) : "memory");
}
__device__ __forceinline__ void cpa_commit() {
    asm volatile("cp.async.commit_group;" ::: "memory");
}
template <int N> __device__ __forceinline__ void cpa_wait() {
    asm volatile("cp.async.wait_group %0;" :: "n"(N) : "memory");
}

// fp32x4 -> packed bf16 hi plane + lo plane (2-way split)
__device__ __forceinline__ void split_pack(float4 v, uint2& hi, uint2& lo) {
    __nv_bfloat16 bx = __float2bfloat16_rn(v.x);
    __nv_bfloat16 by = __float2bfloat16_rn(v.y);
    __nv_bfloat16 bz = __float2bfloat16_rn(v.z);
    __nv_bfloat16 bw = __float2bfloat16_rn(v.w);
    hi.x = ((uint32_t)__bfloat16_as_ushort(by) << 16) | __bfloat16_as_ushort(bx);
    hi.y = ((uint32_t)__bfloat16_as_ushort(bw) << 16) | __bfloat16_as_ushort(bz);
    __nv_bfloat16 lx = __float2bfloat16_rn(v.x - __bfloat162float(bx));
    __nv_bfloat16 ly = __float2bfloat16_rn(v.y - __bfloat162float(by));
    __nv_bfloat16 lz = __float2bfloat16_rn(v.z - __bfloat162float(bz));
    __nv_bfloat16 lw = __float2bfloat16_rn(v.w - __bfloat162float(bw));
    lo.x = ((uint32_t)__bfloat16_as_ushort(ly) << 16) | __bfloat16_as_ushort(lx);
    lo.y = ((uint32_t)__bfloat16_as_ushort(lw) << 16) | __bfloat16_as_ushort(lz);
}

// ================= split inputs: fp32 -> (hi, lo) bf16 planes =================
// Also clears g_selmask (folded-in former clear_kernel).
__global__ __launch_bounds__(256) void split_kernel(
    const float* __restrict__ s0, const float* __restrict__ s1, const float* __restrict__ s2,
    int base) {
    const int sid = base + blockIdx.y;
    const float* s = (blockIdx.y == 0) ? s0 : (blockIdx.y == 1) ? s1 : s2;
    __nv_bfloat16 *dh, *dl;
    int n4;
    if (sid < 3) { dh = g_xh[sid]; dl = g_xl[sid]; n4 = MM * DD / 4; }
    else         { dh = g_wh[sid - 3]; dl = g_wl[sid - 3]; n4 = DD * DD / 4; }
    int idx = blockIdx.x * 256 + threadIdx.x;
    if (base == 0 && blockIdx.y == 0 && idx < BB * LL) g_selmask[idx] = 0u;
    if (idx >= n4) return;
    float4 val = ((const float4*)s)[idx];
    uint2 hi, lo;
    split_pack(val, hi, lo);
    ((uint2*)dh)[idx] = hi;
    ((uint2*)dl)[idx] = lo;
}

// ================= fused projections via cp.async + mma.sync ==================
#define PROJ_STG 32768
#define PROJ_DSMEM (3*PROJ_STG)

__global__ void __launch_bounds__(256, 2) proj_mma(
    const float* __restrict__ bi0, const float* __restrict__ bi1, const float* __restrict__ bi2) {
    extern __shared__ char sm[];
    const uint32_t sb = smem_u32(sm);
    const int z = blockIdx.z;
    const float* bias = (z == 0) ? bi0 : (z == 1) ? bi1 : bi2;
    float* __restrict__ Y = g_qkv[z];
    const int tid = threadIdx.x, lane = tid & 31, wid = tid >> 5;
    const int bm = blockIdx.y * 128, bn = blockIdx.x * 128;
    const int m0 = (wid >> 1) * 32, n0 = (wid & 1) * 64;

    float c[2][8][4];
#pragma unroll
    for (int i = 0; i < 2; ++i)
#pragma unroll
        for (int j = 0; j < 8; ++j)
#pragma unroll
            for (int k = 0; k < 4; ++k) c[i][j][k] = 0.f;

    const char* pXh[2]; const char* pXl[2]; const char* pWh[2]; const char* pWl[2];
    uint32_t doff[2];
#pragma unroll
    for (int i = 0; i < 2; ++i) {
        int idx = tid + 256 * i;
        int r = idx >> 2, seg = idx & 3;
        pXh[i] = (const char*)(g_xh[z] + (size_t)(bm + r) * DD + seg * 8);
        pXl[i] = (const char*)(g_xl[z] + (size_t)(bm + r) * DD + seg * 8);
        pWh[i] = (const char*)(g_wh[z] + (size_t)(bn + r) * DD + seg * 8);
        pWl[i] = (const char*)(g_wl[z] + (size_t)(bn + r) * DD + seg * 8);
        doff[i] = (uint32_t)r * 64 + (uint32_t)((seg ^ ((r >> 1) & 3)) << 4);
    }

    auto issue = [&](int kt) {
        uint32_t off = (uint32_t)kt * 64;
        uint32_t stg = sb + (uint32_t)(kt % 3) * PROJ_STG;
#pragma unroll
        for (int i = 0; i < 2; ++i) {
            uint32_t base = stg + doff[i];
            cpa16(base, pXh[i] + off);
            cpa16(base + 8192, pXl[i] + off);
            cpa16(base + 16384, pWh[i] + off);
            cpa16(base + 24576, pWl[i] + off);
        }
        cpa_commit();
    };

    const int hi16 = (lane >> 4) & 1;
    uint32_t aRB[2]; int aX[2];
#pragma unroll
    for (int i = 0; i < 2; ++i) {
        int r = m0 + (lane & 15) + i * 16;
        aRB[i] = (uint32_t)r * 64;
        aX[i] = (r >> 1) & 3;
    }
    uint32_t bRB[4]; int bX[4];
#pragma unroll
    for (int jh = 0; jh < 4; ++jh) {
        int r = n0 + jh * 16 + (lane & 15);
        bRB[jh] = (uint32_t)r * 64;
        bX[jh] = (r >> 1) & 3;
    }

    issue(0); issue(1);

#pragma unroll 1
    for (int kt = 0; kt < 32; ++kt) {
        if (kt < 31) cpa_wait<1>();
        else cpa_wait<0>();
        __syncthreads();
        if (kt + 2 < 32) issue(kt + 2);

        const uint32_t A = sb + (uint32_t)(kt % 3) * PROJ_STG;
#pragma unroll
        for (int s = 0; s < 2; ++s) {
            const int slot = s * 2 + hi16;
            uint32_t ah[2][4], al[2][4];
#pragma unroll
            for (int i = 0; i < 2; ++i) {
                uint32_t ao = aRB[i] + (uint32_t)((slot ^ aX[i]) << 4);
                ldsm4(ah[i], A + ao);
                ldsm4(al[i], A + 8192 + ao);
            }
#pragma unroll
            for (int jh = 0; jh < 4; ++jh) {
                uint32_t bo = bRB[jh] + (uint32_t)((slot ^ bX[jh]) << 4);
                uint32_t bh[2][2], bl[2][2];
                {
                    uint32_t q[4];
                    ldsm4(q, A + 16384 + bo);
                    bh[0][0] = q[0]; bh[0][1] = q[2]; bh[1][0] = q[1]; bh[1][1] = q[3];
                    ldsm4(q, A + 24576 + bo);
                    bl[0][0] = q[0]; bl[0][1] = q[2]; bl[1][0] = q[1]; bl[1][1] = q[3];
                }
#pragma unroll
                for (int i = 0; i < 2; ++i)
#pragma unroll
                    for (int jj = 0; jj < 2; ++jj) {
                        float* cc = c[i][jh * 2 + jj];
                        mma16816(cc, ah[i], bh[jj]);
                        mma16816(cc, ah[i], bl[jj]);
                        mma16816(cc, al[i], bh[jj]);
                    }
            }
        }
    }

    // epilogue
    __nv_bfloat16* qh = (z < 2) ? g_qkh[z] : 0;
    __nv_bfloat16* ql = (z < 2) ? g_qkl[z] : 0;
#pragma unroll
    for (int i = 0; i < 2; ++i) {
        int r0 = bm + m0 + i * 16 + (lane >> 2);
#pragma unroll
        for (int j = 0; j < 8; ++j) {
            int col = bn + n0 + j * 8 + (lane & 3) * 2;
            float bx = bias[col], by = bias[col + 1];
#pragma unroll
            for (int hh = 0; hh < 2; ++hh) {
                int rr = r0 + hh * 8;
                float v0 = c[i][j][hh * 2] + bx, v1 = c[i][j][hh * 2 + 1] + by;
                *(float2*)(Y + (size_t)rr * DD + col) = make_float2(v0, v1);
                if (z < 2) {
                    __nv_bfloat16 h0 = __float2bfloat16_rn(v0);
                    __nv_bfloat16 h1 = __float2bfloat16_rn(v1);
                    __nv_bfloat16 l0 = __float2bfloat16_rn(v0 - __bfloat162float(h0));
                    __nv_bfloat16 l1 = __float2bfloat16_rn(v1 - __bfloat162float(h1));
                    *(uint32_t*)(qh + (size_t)rr * DD + col) =
                        ((uint32_t)__bfloat16_as_ushort(h1) << 16) | __bfloat16_as_ushort(h0);
                    *(uint32_t*)(ql + (size_t)rr * DD + col) =
                        ((uint32_t)__bfloat16_as_ushort(l1) << 16) | __bfloat16_as_ushort(l0);
                }
            }
        }
    }
}

// ================= sparsity v2 (round-13) =====================================
#define SPQ 18432
#define SPK0 36864
#define SPK_STG 18432
#define SP_DSMEM (SPK0 + 2*SPK_STG)

__global__ void __launch_bounds__(256, 2) sparsity_mma() {
    extern __shared__ char sm[];
    const uint32_t sb = smem_u32(sm);
    const int tid = threadIdx.x, lane = tid & 31, wid = tid >> 5;
    const int b = blockIdx.z, h = blockIdx.y, q0 = blockIdx.x * 128;
    const int m0 = wid * 16;
    const __nv_bfloat16* __restrict__ Qh = g_qkh[0];
    const __nv_bfloat16* __restrict__ Ql = g_qkl[0];
    const __nv_bfloat16* __restrict__ Kh = g_qkh[1];
    const __nv_bfloat16* __restrict__ Kl = g_qkl[1];

    auto issueK = [&](int kt) {
        uint32_t base = sb + SPK0 + (uint32_t)(kt & 1) * SPK_STG;
#pragma unroll
        for (int i = 0; i < 2; ++i) {
            int idx = tid + 256 * i;
            int r = idx >> 3, seg = idx & 7;
            uint32_t doff = (uint32_t)r * 144 + seg * 16;
            size_t src = (size_t)(b * LL + kt * 64 + r) * DD + h * HD + seg * 8;
            cpa16(base + doff, Kh + src);
            cpa16(base + 9216 + doff, Kl + src);
        }
        cpa_commit();
    };

    {
#pragma unroll
        for (int i = 0; i < 4; ++i) {
            int idx = tid + 256 * i;
            int r = idx >> 3, seg = idx & 7;
            uint32_t doff = (uint32_t)r * 144 + seg * 16;
            size_t src = (size_t)(b * LL + q0 + r) * DD + h * HD + seg * 8;
            cpa16(sb + doff, Qh + src);
            cpa16(sb + SPQ + doff, Ql + src);
        }
    }
    issueK(0);
    cpa_wait<0>();
    __syncthreads();

    uint32_t qa[4][2][4];
    {
        const uint32_t arow = sb + (uint32_t)(m0 + (lane & 15)) * 144 + ((lane & 16) ? 16 : 0);
#pragma unroll
        for (int s = 0; s < 4; ++s) {
            ldsm4(qa[s][0], arow + s * 32);
            ldsm4(qa[s][1], arow + SPQ + s * 32);
        }
    }

    uint32_t brow[4];
#pragma unroll
    for (int jh = 0; jh < 4; ++jh)
        brow[jh] = (uint32_t)(jh * 16 + (lane & 15)) * 144 + ((lane & 16) ? 16 : 0);

    float rmax[2] = {-FLT_MAX, -FLT_MAX}, rsum[2] = {0.f, 0.f};

#pragma unroll 1
    for (int kt = 0; kt < 32; ++kt) {
        if (kt + 1 < 32) issueK(kt + 1);
        const uint32_t K = sb + SPK0 + (uint32_t)(kt & 1) * SPK_STG;
        float c[4][2][4];
#pragma unroll
        for (int jh = 0; jh < 4; ++jh)
#pragma unroll
            for (int jj = 0; jj < 2; ++jj)
#pragma unroll
                for (int k = 0; k < 4; ++k) c[jh][jj][k] = 0.f;

#pragma unroll
        for (int s = 0; s < 4; ++s) {
            const uint32_t ko = s * 32;
#pragma unroll
            for (int jh = 0; jh < 4; ++jh) {
                uint32_t bh[2][2], bl[2][2];
                {
                    uint32_t q[4];
                    ldsm4(q, K + brow[jh] + ko);
                    bh[0][0] = q[0]; bh[0][1] = q[2]; bh[1][0] = q[1]; bh[1][1] = q[3];
                    ldsm4(q, K + 9216 + brow[jh] + ko);
                    bl[0][0] = q[0]; bl[0][1] = q[2]; bl[1][0] = q[1]; bl[1][1] = q[3];
                }
#pragma unroll
                for (int jj = 0; jj < 2; ++jj) {
                    float* cc = c[jh][jj];
                    mma16816(cc, qa[s][0], bh[jj]);
                    mma16816(cc, qa[s][0], bl[jj]);
                    mma16816(cc, qa[s][1], bh[jj]);
                }
            }
        }
#pragma unroll
        for (int jh = 0; jh < 4; ++jh)
#pragma unroll
            for (int jj = 0; jj < 2; ++jj) {
                float x0 = c[jh][jj][0], y0 = c[jh][jj][1];
                rmax[0] = fmaxf(rmax[0], fmaxf(x0, y0));
                rsum[0] += x0 + y0;
                float x1 = c[jh][jj][2], y1 = c[jh][jj][3];
                rmax[1] = fmaxf(rmax[1], fmaxf(x1, y1));
                rsum[1] += x1 + y1;
            }
        cpa_wait<0>();
        __syncthreads();
    }

#pragma unroll
    for (int s = 0; s < 2; ++s) {
        rmax[s] = fmaxf(rmax[s], __shfl_xor_sync(0xffffffffu, rmax[s], 1));
        rmax[s] = fmaxf(rmax[s], __shfl_xor_sync(0xffffffffu, rmax[s], 2));
        rsum[s] += __shfl_xor_sync(0xffffffffu, rsum[s], 1);
        rsum[s] += __shfl_xor_sync(0xffffffffu, rsum[s], 2);
    }
    if ((lane & 3) == 0) {
#pragma unroll
        for (int s = 0; s < 2; ++s) {
            int row = m0 + s * 8 + (lane >> 2);
            g_sp[(b * HH + h) * LL + q0 + row] =
                SCALE * rmax[s] - SCALE * rsum[s] * (1.0f / (float)LL);
        }
    }
}

// ---------------- top-40 per (b,h): single warp, barrier-free -----------------
__global__ __launch_bounds__(32) void topk_kernel() {
    const int bh = blockIdx.x;
    const int b = bh >> 4, h = bh & 15;
    __shared__ float sp[LL];
    const int lane = threadIdx.x;
    for (int j = lane; j < LL; j += 32) sp[j] = g_sp[bh * LL + j];
    __syncwarp();
    for (int it = 0; it < TOPU; ++it) {
        float bv = -FLT_MAX; int bi = 1 << 30;
#pragma unroll 8
        for (int jj = 0; jj < 64; ++jj) {
            int j = lane + jj * 32;
            float v = sp[j];
            if (v > bv) { bv = v; bi = j; }
        }
#pragma unroll
        for (int o = 16; o > 0; o >>= 1) {
            float ov = __shfl_xor_sync(0xffffffffu, bv, o);
            int oi = __shfl_xor_sync(0xffffffffu, bi, o);
            if (ov > bv || (ov == bv && oi < bi)) { bv = ov; bi = oi; }
        }
        if (lane == 0) {
            g_topk[bh * TOPU + it] = bi;
            sp[bi] = -FLT_MAX;
            int row = b * LL + bi;
            atomicOr(&g_selmask[row], 1u << h);
            g_selu[row * HH + h] = it;
        }
        __syncwarp();
    }
}

// ---------------- attention over the top queries (AQ=4) ----------------
__global__ __launch_bounds__(256) void attn_kernel() {
    const int b = blockIdx.z, h = blockIdx.y, ut = blockIdx.x;
    const int bh = b * HH + h;
    __shared__ float Qs[4][64];
    __shared__ float P[4][LL];
    __shared__ float red[4][8];
    __shared__ float gmx[4], gsm[4];
    __shared__ float cred[8][4][64];
    const float* __restrict__ gq = g_qkv[0];
    const float* __restrict__ gk = g_qkv[1];
    const float* __restrict__ gv = g_qkv[2];
    const int tid = threadIdx.x, lane = tid & 31, wp = tid >> 5;
    {
        int u = tid >> 6, d = tid & 63;
        int qi = g_topk[bh * TOPU + ut * 4 + u];
        Qs[u][d] = gq[((size_t)(b * LL + qi)) * DD + h * HD + d];
    }
    __syncthreads();
    const float* Kb = gk + (size_t)(b * LL) * DD + h * HD;
    float lm[4] = {-FLT_MAX, -FLT_MAX, -FLT_MAX, -FLT_MAX};
#pragma unroll
    for (int j = 0; j < 8; ++j) {
        int k = tid + 256 * j;
        const float4* kr = (const float4*)(Kb + (size_t)k * DD);
        float s[4] = {0.f, 0.f, 0.f, 0.f};
#pragma unroll
        for (int dv = 0; dv < 16; ++dv) {
            float4 kv = kr[dv];
#pragma unroll
            for (int u = 0; u < 4; ++u)
                s[u] += Qs[u][dv * 4 + 0] * kv.x + Qs[u][dv * 4 + 1] * kv.y +
                        Qs[u][dv * 4 + 2] * kv.z + Qs[u][dv * 4 + 3] * kv.w;
        }
#pragma unroll
        for (int u = 0; u < 4; ++u) {
            float sv = s[u] * SCALE;
            P[u][k] = sv;
            lm[u] = fmaxf(lm[u], sv);
        }
    }
#pragma unroll
    for (int u = 0; u < 4; ++u) {
#pragma unroll
        for (int o = 16; o > 0; o >>= 1) lm[u] = fmaxf(lm[u], __shfl_xor_sync(0xffffffffu, lm[u], o));
        if (lane == 0) red[u][wp] = lm[u];
    }
    __syncthreads();
    if (tid < 4) {
        float m = red[tid][0];
        for (int w = 1; w < 8; ++w) m = fmaxf(m, red[tid][w]);
        gmx[tid] = m;
    }
    __syncthreads();
    float ls[4] = {0.f, 0.f, 0.f, 0.f};
#pragma unroll
    for (int j = 0; j < 8; ++j) {
        int k = tid + 256 * j;
#pragma unroll
        for (int u = 0; u < 4; ++u) {
            float e = expf(P[u][k] - gmx[u]);
            P[u][k] = e;
            ls[u] += e;
        }
    }
#pragma unroll
    for (int u = 0; u < 4; ++u) {
#pragma unroll
        for (int o = 16; o > 0; o >>= 1) ls[u] += __shfl_xor_sync(0xffffffffu, ls[u], o);
        if (lane == 0) red[u][wp] = ls[u];
    }
    __syncthreads();
    if (tid < 4) {
        float s = 0.f;
        for (int w = 0; w < 8; ++w) s += red[tid][w];
        gsm[tid] = s;
    }
    __syncthreads();
    const float* Vb = gv + (size_t)(b * LL) * DD + h * HD;
    const int d0 = lane * 2;
    float c[4][2] = {{0.f,0.f},{0.f,0.f},{0.f,0.f},{0.f,0.f}};
    const int k0 = wp * 256;
    for (int kk = 0; kk < 256; ++kk) {
        int k = k0 + kk;
        float2 v = *(const float2*)(Vb + (size_t)k * DD + d0);
#pragma unroll
        for (int u = 0; u < 4; ++u) {
            float p = P[u][k];
            c[u][0] += p * v.x;
            c[u][1] += p * v.y;
        }
    }
#pragma unroll
    for (int u = 0; u < 4; ++u) {
        cred[wp][u][d0] = c[u][0];
        cred[wp][u][d0 + 1] = c[u][1];
    }
    __syncthreads();
    {
        int u = tid >> 6, d = tid & 63;
        float s = 0.f;
#pragma unroll
        for (int w = 0; w < 8; ++w) s += cred[w][u][d];
        g_ctx[((size_t)bh * TOPU + ut * 4 + u) * HD + d] = s / gsm[u];
    }
}

// ---------------- base mean: two-stage deterministic reduction ----------------
__global__ void base_part() {
    int b = blockIdx.y, seg = blockIdx.z;
    int c = blockIdx.x * 256 + threadIdx.x;
    const float* p = g_qkv[2] + (size_t)b * LL * DD + (size_t)seg * 128 * DD + c;
    float s = 0.f;
#pragma unroll 4
    for (int l = 0; l < 128; ++l) s += p[(size_t)l * DD];
    g_basepart[seg][b * DD + c] = s;
}
__global__ void base_fin() {
    int i = blockIdx.x * 256 + threadIdx.x;
    float s = 0.f;
#pragma unroll
    for (int seg = 0; seg < 16; ++seg) s += g_basepart[seg][i];
    g_base[i] = s * (1.0f / (float)LL);
}

// ---------------- base_out = base_row @ Wo^T + bo ----------------
__global__ __launch_bounds__(256) void baseout_kernel(const float* __restrict__ Wo,
                                                      const float* __restrict__ bo) {
    int b = blockIdx.y;
    int n = blockIdx.x * 256 + threadIdx.x;
    __shared__ float br[DD];
    for (int j = threadIdx.x; j < DD; j += 256) br[j] = g_base[b * DD + j];
    __syncthreads();
    const float4* wr = (const float4*)(Wo + (size_t)n * DD);
    const float4* b4 = (const float4*)br;
    float s = bo[n];
    for (int c = 0; c < DD / 4; ++c) {
        float4 w = wr[c], v = b4[c];
        s += w.x * v.x + w.y * v.y + w.z * v.z + w.w * v.w;
    }
    g_baseout[b * DD + n] = s;
}

// ---------------- deltaout: (ctx - base) @ Wo_slice^T per (bh, u) -------------
// grid (4 tiles, 32 bh), 256 threads. smem: delta[40][64] + Wo tile [256][65].
#define DO_DSMEM ((40*64 + 256*65) * 4)

__global__ __launch_bounds__(256) void deltaout_kernel(const float* __restrict__ Wo) {
    extern __shared__ float dsm[];
    float* sdelta = dsm;               // [40][64]
    float* tile = dsm + 40 * 64;       // [256][65]
    const int t = blockIdx.x, bh = blockIdx.y;
    const int b = bh >> 4, h = bh & 15;
    const int tid = threadIdx.x;
    const int n0 = t * 256;

    for (int idx = tid; idx < TOPU * HD; idx += 256) {
        int u = idx >> 6, d = idx & 63;
        sdelta[idx] = g_ctx[((size_t)bh * TOPU + u) * HD + d] - g_base[b * DD + h * HD + d];
    }
    // coalesced tile load: 256 rows x 64 cols
#pragma unroll
    for (int i = 0; i < 32; ++i) {
        int idx = tid + 256 * i;
        int r = idx >> 5, c2 = idx & 31;
        float2 v = *(const float2*)(Wo + (size_t)(n0 + r) * DD + h * HD + c2 * 2);
        tile[r * 65 + c2 * 2] = v.x;
        tile[r * 65 + c2 * 2 + 1] = v.y;
    }
    __syncthreads();
    float acc[TOPU];
#pragma unroll
    for (int u = 0; u < TOPU; ++u) acc[u] = 0.f;
#pragma unroll 8
    for (int d = 0; d < HD; ++d) {
        float td = tile[tid * 65 + d];
#pragma unroll
        for (int u = 0; u < TOPU; ++u) acc[u] += td * sdelta[u * 64 + d];
    }
#pragma unroll
    for (int u = 0; u < TOPU; ++u)
        g_dout[((size_t)bh * TOPU + u) * DD + n0 + tid] = acc[u];
}

// ---------------- final output: stream baseout + selected deltaout rows -------
__global__ __launch_bounds__(256) void output_kernel(float* __restrict__ out) {
    const int row = blockIdx.x;
    const int b = row >> 11;
    const int tid = threadIdx.x;
    float4 o = *(const float4*)(g_baseout + b * DD + tid * 4);
    unsigned mask = g_selmask[row];
    while (mask) {
        int h = __ffs(mask) - 1;
        mask &= mask - 1;
        int u = g_selu[row * HH + h];
        int bh = b * HH + h;
        float4 d = *(const float4*)(g_dout + ((size_t)bh * TOPU + u) * DD + tid * 4);
        o.x += d.x; o.y += d.y; o.z += d.z; o.w += d.w;
    }
    *(float4*)(out + (size_t)row * DD + tid * 4) = o;
}

// ---------------- launch ----------------
extern "C" void kernel_launch(void* const* d_in, const int* in_sizes, int n_in,
                              void* d_out, int out_size) {
    const float* query = (const float*)d_in[0];
    const float* key_t = (const float*)d_in[1];
    const float* value = (const float*)d_in[2];
    const float* Wq = (const float*)d_in[3];
    const float* bq = (const float*)d_in[4];
    const float* Wk = (const float*)d_in[5];
    const float* bk = (const float*)d_in[6];
    const float* Wv = (const float*)d_in[7];
    const float* bv = (const float*)d_in[8];
    const float* Wo = (const float*)d_in[9];
    const float* bo = (const float*)d_in[10];
    float* out = (float*)d_out;

    cudaFuncSetAttribute(proj_mma, cudaFuncAttributeMaxDynamicSharedMemorySize, PROJ_DSMEM);
    cudaFuncSetAttribute(sparsity_mma, cudaFuncAttributeMaxDynamicSharedMemorySize, SP_DSMEM);
    cudaFuncSetAttribute(deltaout_kernel, cudaFuncAttributeMaxDynamicSharedMemorySize, DO_DSMEM);

    split_kernel<<<dim3(4096, 3), 256>>>(query, key_t, value, 0);     // 1 (also clears selmask)
    split_kernel<<<dim3(1024, 3), 256>>>(Wq, Wk, Wv, 3);              // 2
    proj_mma<<<dim3(8, 32, 3), 256, PROJ_DSMEM>>>(bq, bk, bv);        // 3
    sparsity_mma<<<dim3(LL / 128, HH, BB), 256, SP_DSMEM>>>();        // 4 (profiled)
    topk_kernel<<<BB * HH, 32>>>();                                   // 5
    attn_kernel<<<dim3(TOPU / 4, HH, BB), 256>>>();                   // 6
    base_part<<<dim3(DD / 256, BB, 16), 256>>>();                     // 7
    base_fin<<<BB * DD / 256, 256>>>();                               // 8
    baseout_kernel<<<dim3(DD / 256, BB), 256>>>(Wo, bo);              // 9
    deltaout_kernel<<<dim3(4, BB * HH), 256, DO_DSMEM>>>(Wo);         // 10
    output_kernel<<<BB * LL, 256>>>(out);                             // 11
}